// round 1
// baseline (speedup 1.0000x reference)
#include <cuda_runtime.h>
#include <cuda_bf16.h>
#include <math.h>

// Shapes are fixed by the problem: B=4, S=2048, D=1024, H=16, dh=64.
#define BATCH     4
#define SEQ       2048
#define DMODEL    1024
#define NHEADS    16
#define HDIM      64
#define MTOT      (BATCH * SEQ)      // 8192
#define KDIM      DMODEL             // 1024
#define NDIM      DMODEL             // 1024

// Scratch (device globals: allocation-free per harness rules)
__device__ float g_q[BATCH * NHEADS * SEQ * HDIM];   // [b,h,s,d]
__device__ float g_k[BATCH * NHEADS * SEQ * HDIM];
__device__ float g_v[BATCH * NHEADS * SEQ * HDIM];
__device__ float g_o[BATCH * SEQ * DMODEL];          // [b,s,h*dh]
__device__ float g_cos[SEQ * (HDIM / 2)];
__device__ float g_sin[SEQ * (HDIM / 2)];

// ---------------------------------------------------------------------------
// RoPE table: cos/sin(pos * theta^(-2f/64)) for pos in [0,S), f in [0,32)
// ---------------------------------------------------------------------------
__global__ void rope_table_kernel(const int* __restrict__ tpos) {
    int s = blockIdx.x;
    int f = threadIdx.x;                         // 0..31
    double inv = exp(-(2.0 * (double)f / (double)HDIM) * log(10000.0));
    double a = (double)tpos[s] * inv;
    g_cos[s * 32 + f] = (float)cos(a);
    g_sin[s * 32 + f] = (float)sin(a);
}

// ---------------------------------------------------------------------------
// 128x128 tiled fp32 GEMM: C[m][n] = sum_k A[m][k] * W[n][k]   (both row-major,
// K contiguous). 256 threads, 8x8 per thread in split-half layout (two 4-col
// groups at tx*4 and 64+tx*4 -> conflict-free float4 smem reads).
// mode 0: write Q with RoPE into g_q[b,h,s,d]
// mode 1: write K with RoPE into g_k
// mode 2: write V into g_v
// mode 3: plain store into Cout (final projection). A==nullptr means read g_o.
// ---------------------------------------------------------------------------
#define KT 16

__global__ __launch_bounds__(256)
void gemm128(const float* __restrict__ A, const float* __restrict__ W,
             float* __restrict__ Cout, int mode) {
    __shared__ float As[KT][128];
    __shared__ float Bs[KT][128];

    const float* Ap = A ? A : g_o;

    const int tid = threadIdx.x;
    const int ty = tid >> 4, tx = tid & 15;
    const int m0 = blockIdx.y * 128, n0 = blockIdx.x * 128;

    const int lr = tid >> 1;           // 0..127 : tile row loaded by this thread
    const int lk = (tid & 1) * 8;      // 0 or 8 : k-offset within tile

    float acc[8][8];
#pragma unroll
    for (int i = 0; i < 8; i++)
#pragma unroll
        for (int j = 0; j < 8; j++) acc[i][j] = 0.f;

    const float* Arow = Ap + (size_t)(m0 + lr) * KDIM + lk;
    const float* Wrow = W + (size_t)(n0 + lr) * KDIM + lk;

    for (int kt = 0; kt < KDIM; kt += KT) {
        float4 a0 = *(const float4*)(Arow + kt);
        float4 a1 = *(const float4*)(Arow + kt + 4);
        float4 b0 = *(const float4*)(Wrow + kt);
        float4 b1 = *(const float4*)(Wrow + kt + 4);
        __syncthreads();   // previous tile's compute must finish before overwrite
        As[lk + 0][lr] = a0.x; As[lk + 1][lr] = a0.y;
        As[lk + 2][lr] = a0.z; As[lk + 3][lr] = a0.w;
        As[lk + 4][lr] = a1.x; As[lk + 5][lr] = a1.y;
        As[lk + 6][lr] = a1.z; As[lk + 7][lr] = a1.w;
        Bs[lk + 0][lr] = b0.x; Bs[lk + 1][lr] = b0.y;
        Bs[lk + 2][lr] = b0.z; Bs[lk + 3][lr] = b0.w;
        Bs[lk + 4][lr] = b1.x; Bs[lk + 5][lr] = b1.y;
        Bs[lk + 6][lr] = b1.z; Bs[lk + 7][lr] = b1.w;
        __syncthreads();

#pragma unroll
        for (int kk = 0; kk < KT; kk++) {
            float a[8], b[8];
            *(float4*)(a)     = *(const float4*)&As[kk][ty * 4];
            *(float4*)(a + 4) = *(const float4*)&As[kk][64 + ty * 4];
            *(float4*)(b)     = *(const float4*)&Bs[kk][tx * 4];
            *(float4*)(b + 4) = *(const float4*)&Bs[kk][64 + tx * 4];
#pragma unroll
            for (int i = 0; i < 8; i++)
#pragma unroll
                for (int j = 0; j < 8; j++)
                    acc[i][j] = fmaf(a[i], b[j], acc[i][j]);
        }
    }

    // split-half index maps
    // row_i = m0 + ty*4 + (i&3) + (i>>2)*64 ; col_j = n0 + tx*4 + (j&3) + (j>>2)*64
    if (mode == 3) {
#pragma unroll
        for (int i = 0; i < 8; i++) {
            int m = m0 + ty * 4 + (i & 3) + ((i >> 2) << 6);
            float* crow0 = Cout + (size_t)m * NDIM + n0 + tx * 4;
            float* crow1 = Cout + (size_t)m * NDIM + n0 + 64 + tx * 4;
            *(float4*)crow0 = make_float4(acc[i][0], acc[i][1], acc[i][2], acc[i][3]);
            *(float4*)crow1 = make_float4(acc[i][4], acc[i][5], acc[i][6], acc[i][7]);
        }
    } else {
        float* dst = (mode == 0) ? g_q : (mode == 1) ? g_k : g_v;
#pragma unroll
        for (int i = 0; i < 8; i++) {
            int m = m0 + ty * 4 + (i & 3) + ((i >> 2) << 6);
            int b = m >> 11;          // / 2048
            int s = m & 2047;
            if (mode < 2) {
                // RoPE: pairs within each 4-col group (tx*4 is even-aligned)
#pragma unroll
                for (int jp = 0; jp < 4; jp++) {
                    int grp = jp >> 1;                 // 0 or 1
                    int c0 = n0 + grp * 64 + tx * 4 + (jp & 1) * 2;
                    int h = c0 >> 6;
                    int d0 = c0 & 63;                  // even
                    float cs = g_cos[s * 32 + (d0 >> 1)];
                    float sn = g_sin[s * 32 + (d0 >> 1)];
                    float v1 = acc[i][grp * 4 + (jp & 1) * 2];
                    float v2 = acc[i][grp * 4 + (jp & 1) * 2 + 1];
                    size_t base = ((size_t)(b * NHEADS + h) * SEQ + s) * HDIM + d0;
                    dst[base]     = v1 * cs - v2 * sn;
                    dst[base + 1] = v1 * sn + v2 * cs;
                }
            } else {
#pragma unroll
                for (int j = 0; j < 8; j++) {
                    int c = n0 + tx * 4 + (j & 3) + ((j >> 2) << 6);
                    int h = c >> 6, d = c & 63;
                    dst[((size_t)(b * NHEADS + h) * SEQ + s) * HDIM + d] = acc[i][j];
                }
            }
        }
    }
}

// ---------------------------------------------------------------------------
// Causal flash attention, 64x64 tiles, fp32, online softmax.
// grid = (S/64, B*H), block = 256 (16x16 threads, 4x4 per thread).
// smem: Q,K,V,P each [64][65] -> 66560 B dynamic.
// ---------------------------------------------------------------------------
#define ATTN_SMEM (4 * 64 * 65 * 4)

__global__ __launch_bounds__(256)
void flash_attn_kernel() {
    extern __shared__ float sm[];
    float (*Qs)[65] = (float (*)[65])(sm);
    float (*Ks)[65] = (float (*)[65])(sm + 64 * 65);
    float (*Vs)[65] = (float (*)[65])(sm + 2 * 64 * 65);
    float (*Ps)[65] = (float (*)[65])(sm + 3 * 64 * 65);

    const int qt = blockIdx.x;
    const int bh = blockIdx.y;          // b*16 + h
    const int tid = threadIdx.x;
    const int ty = tid >> 4, tx = tid & 15;

    const float* Qg = g_q + ((size_t)bh * SEQ + qt * 64) * HDIM;
    for (int t = tid; t < 1024; t += 256) {     // 64*64/4 float4s
        int r = t >> 4, c = (t & 15) * 4;
        float4 v = *(const float4*)(Qg + r * 64 + c);
        Qs[r][c] = v.x; Qs[r][c + 1] = v.y; Qs[r][c + 2] = v.z; Qs[r][c + 3] = v.w;
    }

    float m_i[4], l_i[4], o[4][4];
#pragma unroll
    for (int i = 0; i < 4; i++) {
        m_i[i] = -1e30f; l_i[i] = 0.f;
#pragma unroll
        for (int j = 0; j < 4; j++) o[i][j] = 0.f;
    }

    for (int kt = 0; kt <= qt; kt++) {
        const float* Kg = g_k + ((size_t)bh * SEQ + kt * 64) * HDIM;
        const float* Vg = g_v + ((size_t)bh * SEQ + kt * 64) * HDIM;
        __syncthreads();    // previous iter's P@V (and Q-load on iter 0) done
        for (int t = tid; t < 1024; t += 256) {
            int r = t >> 4, c = (t & 15) * 4;
            float4 kv = *(const float4*)(Kg + r * 64 + c);
            Ks[r][c] = kv.x; Ks[r][c + 1] = kv.y; Ks[r][c + 2] = kv.z; Ks[r][c + 3] = kv.w;
            float4 vv = *(const float4*)(Vg + r * 64 + c);
            Vs[r][c] = vv.x; Vs[r][c + 1] = vv.y; Vs[r][c + 2] = vv.z; Vs[r][c + 3] = vv.w;
        }
        __syncthreads();

        float s[4][4];
#pragma unroll
        for (int i = 0; i < 4; i++)
#pragma unroll
            for (int j = 0; j < 4; j++) s[i][j] = 0.f;

#pragma unroll 8
        for (int d = 0; d < 64; d++) {
            float a[4], bb[4];
#pragma unroll
            for (int i = 0; i < 4; i++) a[i] = Qs[ty * 4 + i][d];
#pragma unroll
            for (int j = 0; j < 4; j++) bb[j] = Ks[tx * 4 + j][d];
#pragma unroll
            for (int i = 0; i < 4; i++)
#pragma unroll
                for (int j = 0; j < 4; j++)
                    s[i][j] = fmaf(a[i], bb[j], s[i][j]);
        }

        const float scale = 0.125f;   // 1/sqrt(64)
        if (kt == qt) {
#pragma unroll
            for (int i = 0; i < 4; i++)
#pragma unroll
                for (int j = 0; j < 4; j++)
                    s[i][j] = (tx * 4 + j > ty * 4 + i) ? -1e30f : s[i][j] * scale;
        } else {
#pragma unroll
            for (int i = 0; i < 4; i++)
#pragma unroll
                for (int j = 0; j < 4; j++) s[i][j] *= scale;
        }

#pragma unroll
        for (int i = 0; i < 4; i++) {
            float r = fmaxf(fmaxf(s[i][0], s[i][1]), fmaxf(s[i][2], s[i][3]));
#pragma unroll
            for (int off = 1; off < 16; off <<= 1)
                r = fmaxf(r, __shfl_xor_sync(0xffffffffu, r, off));
            float mnew = fmaxf(m_i[i], r);
            float alpha = __expf(m_i[i] - mnew);
            float sum = 0.f;
#pragma unroll
            for (int j = 0; j < 4; j++) {
                float p = __expf(s[i][j] - mnew);
                s[i][j] = p;
                sum += p;
            }
#pragma unroll
            for (int off = 1; off < 16; off <<= 1)
                sum += __shfl_xor_sync(0xffffffffu, sum, off);
            l_i[i] = l_i[i] * alpha + sum;
            m_i[i] = mnew;
#pragma unroll
            for (int j = 0; j < 4; j++) {
                o[i][j] *= alpha;
                Ps[ty * 4 + i][tx * 4 + j] = s[i][j];
            }
        }
        __syncthreads();   // P fully written before P@V

#pragma unroll 8
        for (int c = 0; c < 64; c++) {
            float p[4], vv[4];
#pragma unroll
            for (int i = 0; i < 4; i++) p[i] = Ps[ty * 4 + i][c];
#pragma unroll
            for (int j = 0; j < 4; j++) vv[j] = Vs[c][tx * 4 + j];
#pragma unroll
            for (int i = 0; i < 4; i++)
#pragma unroll
                for (int j = 0; j < 4; j++)
                    o[i][j] = fmaf(p[i], vv[j], o[i][j]);
        }
    }

    const int b = bh >> 4, h = bh & 15;
#pragma unroll
    for (int i = 0; i < 4; i++) {
        int srow = qt * 64 + ty * 4 + i;
        float inv = 1.f / l_i[i];
        float* orow = g_o + ((size_t)b * SEQ + srow) * DMODEL + h * HDIM + tx * 4;
#pragma unroll
        for (int j = 0; j < 4; j++) orow[j] = o[i][j] * inv;
    }
}

// ---------------------------------------------------------------------------
// Launch: rope table -> QKV GEMMs (+RoPE) -> flash attention -> out proj.
// Inputs (metadata order): x, Wq, Wk, Wv, Wo, token_positions. Output fp32.
// ---------------------------------------------------------------------------
extern "C" void kernel_launch(void* const* d_in, const int* in_sizes, int n_in,
                              void* d_out, int out_size) {
    const float* x   = (const float*)d_in[0];
    const float* Wq  = (const float*)d_in[1];
    const float* Wk  = (const float*)d_in[2];
    const float* Wv  = (const float*)d_in[3];
    const float* Wo  = (const float*)d_in[4];
    const int* tpos  = (const int*)d_in[5];
    float* out = (float*)d_out;

    rope_table_kernel<<<SEQ, 32>>>(tpos);

    dim3 gg(NDIM / 128, MTOT / 128);   // (8, 64)
    gemm128<<<gg, 256>>>(x, Wq, nullptr, 0);
    gemm128<<<gg, 256>>>(x, Wk, nullptr, 1);
    gemm128<<<gg, 256>>>(x, Wv, nullptr, 2);

    cudaFuncSetAttribute(flash_attn_kernel,
                         cudaFuncAttributeMaxDynamicSharedMemorySize, ATTN_SMEM);
    flash_attn_kernel<<<dim3(SEQ / 64, BATCH * NHEADS), 256, ATTN_SMEM>>>();

    gemm128<<<gg, 256>>>(nullptr, Wo, out, 3);
}

// round 4
// speedup vs baseline: 1.7182x; 1.7182x over previous
#include <cuda_runtime.h>
#include <cuda_bf16.h>
#include <math.h>
#include <stdint.h>

// Shapes fixed: B=4, S=2048, D=1024, H=16, dh=64.
#define BATCH     4
#define SEQ       2048
#define DMODEL    1024
#define NHEADS    16
#define HDIM      64
#define MTOT      (BATCH * SEQ)      // 8192
#define KDIM      DMODEL
#define NDIM      DMODEL

// Scratch (device globals: allocation-free per harness rules)
__device__ float g_q[BATCH * NHEADS * SEQ * HDIM];
__device__ float g_k[BATCH * NHEADS * SEQ * HDIM];
__device__ float g_v[BATCH * NHEADS * SEQ * HDIM];
__device__ float g_o[BATCH * SEQ * DMODEL];
__device__ float g_cos[SEQ * (HDIM / 2)];
__device__ float g_sin[SEQ * (HDIM / 2)];

// ---------------------------------------------------------------------------
// RoPE table
// ---------------------------------------------------------------------------
__global__ void rope_table_kernel(const int* __restrict__ tpos) {
    int s = blockIdx.x;
    int f = threadIdx.x;
    double inv = exp(-(2.0 * (double)f / (double)HDIM) * log(10000.0));
    double a = (double)tpos[s] * inv;
    g_cos[s * 32 + f] = (float)cos(a);
    g_sin[s * 32 + f] = (float)sin(a);
}

// ---------------------------------------------------------------------------
// tf32 helpers (sm_100 baseline target: mma.sync is available, tcgen05 is NOT)
// ---------------------------------------------------------------------------
__device__ __forceinline__ uint32_t f2tf32(float x) {
    uint32_t u;
    asm("cvt.rna.tf32.f32 %0, %1;" : "=r"(u) : "f"(x));
    return u;
}
__device__ __forceinline__ void mma_tf32(float c[4], const uint32_t a[4],
                                         uint32_t b0, uint32_t b1) {
    asm volatile(
        "mma.sync.aligned.m16n8k8.row.col.f32.tf32.tf32.f32 "
        "{%0,%1,%2,%3}, {%4,%5,%6,%7}, {%8,%9}, {%0,%1,%2,%3};"
        : "+f"(c[0]), "+f"(c[1]), "+f"(c[2]), "+f"(c[3])
        : "r"(a[0]), "r"(a[1]), "r"(a[2]), "r"(a[3]), "r"(b0), "r"(b1));
}

// ---------------------------------------------------------------------------
// tf32 mma.sync GEMM: C[m][n] = sum_k A[m][k] * W[n][k], fp32 in/out.
// CTA tile 128x128, 8 warps (4m x 2n), warp tile 32x64 (2 m-frags x 8 n-frags
// of m16n8k8). K staged in 64-wide chunks, smem pitch 68 (conflict-free:
// 68 mod 32 = 4). Accumulate in registers across all 16 chunks.
// qkv mode (Cout==nullptr): blockIdx.z in {0,1,2} -> Wq/Wk/Wv epilogues
//   (Q,K get RoPE; V plain scatter to [b,h,s,d]).
// proj mode: plain store to Cout, A read from g_o.
// ---------------------------------------------------------------------------
#define KC      64
#define PITCH   68
#define GEMM_SMEM (2 * 128 * PITCH * 4)   // 69632 bytes

__global__ __launch_bounds__(256)
void gemm_mma(const float* __restrict__ A,
              const float* __restrict__ W0, const float* __restrict__ W1,
              const float* __restrict__ W2,
              float* __restrict__ Cout) {
    extern __shared__ __align__(16) uint32_t smu[];
    uint32_t* As = smu;                  // [128][PITCH]
    uint32_t* Bs = smu + 128 * PITCH;    // [128][PITCH]

    const int mode = Cout ? 3 : blockIdx.z;          // 0:Q 1:K 2:V 3:out-proj
    const float* W = (mode == 1) ? W1 : (mode == 2) ? W2 : W0;
    const float* Ap = A ? A : g_o;

    const int tid = threadIdx.x;
    const int warp = tid >> 5, lane = tid & 31;
    const int wm = warp >> 1, wn = warp & 1;         // 4 x 2 warp grid
    const int g = lane >> 2, t = lane & 3;           // groupID / thread-in-group
    const int m0 = blockIdx.y * 128, n0 = blockIdx.x * 128;

    float c[2][8][4];
#pragma unroll
    for (int mf = 0; mf < 2; mf++)
#pragma unroll
        for (int f = 0; f < 8; f++)
#pragma unroll
            for (int i = 0; i < 4; i++) c[mf][f][i] = 0.f;

    for (int ch = 0; ch < 16; ch++) {
        const int kc = ch * KC;
        __syncthreads();   // previous chunk's compute done before overwrite
        // fill: 128x64 fp32 -> tf32 for both tiles; 8 float4 per thread each
#pragma unroll
        for (int j = 0; j < 8; j++) {
            int it = tid + j * 256;       // 0..2047
            int r = it >> 4;              // 0..127
            int kq = (it & 15) << 2;      // 0..60
            float4 fa = *(const float4*)(Ap + (size_t)(m0 + r) * KDIM + kc + kq);
            float4 fb = *(const float4*)(W  + (size_t)(n0 + r) * KDIM + kc + kq);
            uint4 ua = make_uint4(f2tf32(fa.x), f2tf32(fa.y), f2tf32(fa.z), f2tf32(fa.w));
            uint4 ub = make_uint4(f2tf32(fb.x), f2tf32(fb.y), f2tf32(fb.z), f2tf32(fb.w));
            *(uint4*)(As + r * PITCH + kq) = ua;
            *(uint4*)(Bs + r * PITCH + kq) = ub;
        }
        __syncthreads();

#pragma unroll
        for (int ks = 0; ks < 8; ks++) {
            const int kk = ks * 8;
            uint32_t a[2][4];
#pragma unroll
            for (int mf = 0; mf < 2; mf++) {
                int row = wm * 32 + mf * 16 + g;
                a[mf][0] = As[row * PITCH + kk + t];
                a[mf][1] = As[(row + 8) * PITCH + kk + t];
                a[mf][2] = As[row * PITCH + kk + t + 4];
                a[mf][3] = As[(row + 8) * PITCH + kk + t + 4];
            }
#pragma unroll
            for (int f = 0; f < 8; f++) {
                int n = wn * 64 + f * 8 + g;
                uint32_t b0 = Bs[n * PITCH + kk + t];
                uint32_t b1 = Bs[n * PITCH + kk + t + 4];
                mma_tf32(c[0][f], a[0], b0, b1);
                mma_tf32(c[1][f], a[1], b0, b1);
            }
        }
    }

    // Epilogue. Fragment c{0,1}=row g cols {2t,2t+1}; c{2,3}=row g+8 same cols.
    // Column pairs (2t, 2t+1) are exactly RoPE (even, odd) pairs.
#pragma unroll
    for (int mf = 0; mf < 2; mf++) {
#pragma unroll
        for (int f = 0; f < 8; f++) {
            const float* cc = c[mf][f];
            const int col = n0 + wn * 64 + f * 8 + 2 * t;
            const int rbase = m0 + wm * 32 + mf * 16 + g;
#pragma unroll
            for (int half = 0; half < 2; half++) {
                const int m = rbase + half * 8;
                const float v1 = cc[half * 2], v2 = cc[half * 2 + 1];
                if (mode == 3) {
                    *(float2*)(Cout + (size_t)m * NDIM + col) = make_float2(v1, v2);
                } else {
                    const int b = m >> 11, s = m & 2047;
                    const int h = col >> 6, d = col & 63;   // d even
                    const size_t base =
                        ((size_t)(b * NHEADS + h) * SEQ + s) * HDIM + d;
                    if (mode == 2) {
                        *(float2*)(g_v + base) = make_float2(v1, v2);
                    } else {
                        const float cs = g_cos[s * 32 + (d >> 1)];
                        const float sn = g_sin[s * 32 + (d >> 1)];
                        float* dst = mode ? g_k : g_q;
                        *(float2*)(dst + base) =
                            make_float2(v1 * cs - v2 * sn, v1 * sn + v2 * cs);
                    }
                }
            }
        }
    }
}

// ---------------------------------------------------------------------------
// Causal flash attention, 64x64 tiles, fp32, online softmax (round-1 proven).
// ---------------------------------------------------------------------------
#define ATTN_SMEM (4 * 64 * 65 * 4)

__global__ __launch_bounds__(256)
void flash_attn_kernel() {
    extern __shared__ float sm[];
    float (*Qs)[65] = (float (*)[65])(sm);
    float (*Ks)[65] = (float (*)[65])(sm + 64 * 65);
    float (*Vs)[65] = (float (*)[65])(sm + 2 * 64 * 65);
    float (*Ps)[65] = (float (*)[65])(sm + 3 * 64 * 65);

    const int qt = blockIdx.x;
    const int bh = blockIdx.y;
    const int tid = threadIdx.x;
    const int ty = tid >> 4, tx = tid & 15;

    const float* Qg = g_q + ((size_t)bh * SEQ + qt * 64) * HDIM;
    for (int t = tid; t < 1024; t += 256) {
        int r = t >> 4, c = (t & 15) * 4;
        float4 v = *(const float4*)(Qg + r * 64 + c);
        Qs[r][c] = v.x; Qs[r][c + 1] = v.y; Qs[r][c + 2] = v.z; Qs[r][c + 3] = v.w;
    }

    float m_i[4], l_i[4], o[4][4];
#pragma unroll
    for (int i = 0; i < 4; i++) {
        m_i[i] = -1e30f; l_i[i] = 0.f;
#pragma unroll
        for (int j = 0; j < 4; j++) o[i][j] = 0.f;
    }

    for (int kt = 0; kt <= qt; kt++) {
        const float* Kg = g_k + ((size_t)bh * SEQ + kt * 64) * HDIM;
        const float* Vg = g_v + ((size_t)bh * SEQ + kt * 64) * HDIM;
        __syncthreads();
        for (int t = tid; t < 1024; t += 256) {
            int r = t >> 4, c = (t & 15) * 4;
            float4 kv = *(const float4*)(Kg + r * 64 + c);
            Ks[r][c] = kv.x; Ks[r][c + 1] = kv.y; Ks[r][c + 2] = kv.z; Ks[r][c + 3] = kv.w;
            float4 vv = *(const float4*)(Vg + r * 64 + c);
            Vs[r][c] = vv.x; Vs[r][c + 1] = vv.y; Vs[r][c + 2] = vv.z; Vs[r][c + 3] = vv.w;
        }
        __syncthreads();

        float s[4][4];
#pragma unroll
        for (int i = 0; i < 4; i++)
#pragma unroll
            for (int j = 0; j < 4; j++) s[i][j] = 0.f;

#pragma unroll 8
        for (int d = 0; d < 64; d++) {
            float a[4], bb[4];
#pragma unroll
            for (int i = 0; i < 4; i++) a[i] = Qs[ty * 4 + i][d];
#pragma unroll
            for (int j = 0; j < 4; j++) bb[j] = Ks[tx * 4 + j][d];
#pragma unroll
            for (int i = 0; i < 4; i++)
#pragma unroll
                for (int j = 0; j < 4; j++)
                    s[i][j] = fmaf(a[i], bb[j], s[i][j]);
        }

        const float scale = 0.125f;
        if (kt == qt) {
#pragma unroll
            for (int i = 0; i < 4; i++)
#pragma unroll
                for (int j = 0; j < 4; j++)
                    s[i][j] = (tx * 4 + j > ty * 4 + i) ? -1e30f : s[i][j] * scale;
        } else {
#pragma unroll
            for (int i = 0; i < 4; i++)
#pragma unroll
                for (int j = 0; j < 4; j++) s[i][j] *= scale;
        }

#pragma unroll
        for (int i = 0; i < 4; i++) {
            float r = fmaxf(fmaxf(s[i][0], s[i][1]), fmaxf(s[i][2], s[i][3]));
#pragma unroll
            for (int off = 1; off < 16; off <<= 1)
                r = fmaxf(r, __shfl_xor_sync(0xffffffffu, r, off));
            float mnew = fmaxf(m_i[i], r);
            float alpha = __expf(m_i[i] - mnew);
            float sum = 0.f;
#pragma unroll
            for (int j = 0; j < 4; j++) {
                float p = __expf(s[i][j] - mnew);
                s[i][j] = p;
                sum += p;
            }
#pragma unroll
            for (int off = 1; off < 16; off <<= 1)
                sum += __shfl_xor_sync(0xffffffffu, sum, off);
            l_i[i] = l_i[i] * alpha + sum;
            m_i[i] = mnew;
#pragma unroll
            for (int j = 0; j < 4; j++) {
                o[i][j] *= alpha;
                Ps[ty * 4 + i][tx * 4 + j] = s[i][j];
            }
        }
        __syncthreads();

#pragma unroll 8
        for (int c = 0; c < 64; c++) {
            float p[4], vv[4];
#pragma unroll
            for (int i = 0; i < 4; i++) p[i] = Ps[ty * 4 + i][c];
#pragma unroll
            for (int j = 0; j < 4; j++) vv[j] = Vs[c][tx * 4 + j];
#pragma unroll
            for (int i = 0; i < 4; i++)
#pragma unroll
                for (int j = 0; j < 4; j++)
                    o[i][j] = fmaf(p[i], vv[j], o[i][j]);
        }
    }

    const int b = bh >> 4, h = bh & 15;
#pragma unroll
    for (int i = 0; i < 4; i++) {
        int srow = qt * 64 + ty * 4 + i;
        float inv = 1.f / l_i[i];
        float* orow = g_o + ((size_t)b * SEQ + srow) * DMODEL + h * HDIM + tx * 4;
#pragma unroll
        for (int j = 0; j < 4; j++) orow[j] = o[i][j] * inv;
    }
}

// ---------------------------------------------------------------------------
extern "C" void kernel_launch(void* const* d_in, const int* in_sizes, int n_in,
                              void* d_out, int out_size) {
    const float* x  = (const float*)d_in[0];
    const float* Wq = (const float*)d_in[1];
    const float* Wk = (const float*)d_in[2];
    const float* Wv = (const float*)d_in[3];
    const float* Wo = (const float*)d_in[4];
    const int* tpos = (const int*)d_in[5];
    float* out = (float*)d_out;

    rope_table_kernel<<<SEQ, 32>>>(tpos);

    cudaFuncSetAttribute(gemm_mma, cudaFuncAttributeMaxDynamicSharedMemorySize,
                         GEMM_SMEM);
    // Fused QKV: grid.z = 3 selects Wq/Wk/Wv
    dim3 gqkv(NDIM / 128, MTOT / 128, 3);
    gemm_mma<<<gqkv, 256, GEMM_SMEM>>>(x, Wq, Wk, Wv, nullptr);

    cudaFuncSetAttribute(flash_attn_kernel,
                         cudaFuncAttributeMaxDynamicSharedMemorySize, ATTN_SMEM);
    flash_attn_kernel<<<dim3(SEQ / 64, BATCH * NHEADS), 256, ATTN_SMEM>>>();

    dim3 gp(NDIM / 128, MTOT / 128, 1);
    gemm_mma<<<gp, 256, GEMM_SMEM>>>(nullptr, Wo, nullptr, nullptr, out);
}

// round 5
// speedup vs baseline: 2.4918x; 1.4502x over previous
#include <cuda_runtime.h>
#include <cuda_bf16.h>
#include <math.h>
#include <stdint.h>

// Shapes fixed: B=4, S=2048, D=1024, H=16, dh=64.
#define BATCH     4
#define SEQ       2048
#define DMODEL    1024
#define NHEADS    16
#define HDIM      64
#define MTOT      (BATCH * SEQ)      // 8192
#define KDIM      DMODEL
#define NDIM      DMODEL

// Scratch (device globals: allocation-free per harness rules)
__device__ float g_q[BATCH * NHEADS * SEQ * HDIM];
__device__ float g_k[BATCH * NHEADS * SEQ * HDIM];
__device__ float g_v[BATCH * NHEADS * SEQ * HDIM];
__device__ float g_o[BATCH * SEQ * DMODEL];
__device__ float g_cos[SEQ * (HDIM / 2)];
__device__ float g_sin[SEQ * (HDIM / 2)];

// ---------------------------------------------------------------------------
// RoPE table
// ---------------------------------------------------------------------------
__global__ void rope_table_kernel(const int* __restrict__ tpos) {
    int s = blockIdx.x;
    int f = threadIdx.x;
    double inv = exp(-(2.0 * (double)f / (double)HDIM) * log(10000.0));
    double a = (double)tpos[s] * inv;
    g_cos[s * 32 + f] = (float)cos(a);
    g_sin[s * 32 + f] = (float)sin(a);
}

// ---------------------------------------------------------------------------
// tf32 helpers (sm_100 baseline: mma.sync available, tcgen05 is NOT)
// ---------------------------------------------------------------------------
__device__ __forceinline__ uint32_t f2tf32(float x) {
    uint32_t u;
    asm("cvt.rna.tf32.f32 %0, %1;" : "=r"(u) : "f"(x));
    return u;
}
__device__ __forceinline__ void mma_tf32(float c[4], const uint32_t a[4],
                                         uint32_t b0, uint32_t b1) {
    asm volatile(
        "mma.sync.aligned.m16n8k8.row.col.f32.tf32.tf32.f32 "
        "{%0,%1,%2,%3}, {%4,%5,%6,%7}, {%8,%9}, {%0,%1,%2,%3};"
        : "+f"(c[0]), "+f"(c[1]), "+f"(c[2]), "+f"(c[3])
        : "r"(a[0]), "r"(a[1]), "r"(a[2]), "r"(a[3]), "r"(b0), "r"(b1));
}

// ---------------------------------------------------------------------------
// tf32 mma.sync GEMM (round-4 proven): C[m][n] = sum_k A[m][k] * W[n][k].
// ---------------------------------------------------------------------------
#define KC      64
#define PITCH   68
#define GEMM_SMEM (2 * 128 * PITCH * 4)   // 69632 bytes

__global__ __launch_bounds__(256)
void gemm_mma(const float* __restrict__ A,
              const float* __restrict__ W0, const float* __restrict__ W1,
              const float* __restrict__ W2,
              float* __restrict__ Cout) {
    extern __shared__ __align__(16) uint32_t smu[];
    uint32_t* As = smu;                  // [128][PITCH]
    uint32_t* Bs = smu + 128 * PITCH;    // [128][PITCH]

    const int mode = Cout ? 3 : blockIdx.z;          // 0:Q 1:K 2:V 3:out-proj
    const float* W = (mode == 1) ? W1 : (mode == 2) ? W2 : W0;
    const float* Ap = A ? A : g_o;

    const int tid = threadIdx.x;
    const int warp = tid >> 5, lane = tid & 31;
    const int wm = warp >> 1, wn = warp & 1;         // 4 x 2 warp grid
    const int g = lane >> 2, t = lane & 3;
    const int m0 = blockIdx.y * 128, n0 = blockIdx.x * 128;

    float c[2][8][4];
#pragma unroll
    for (int mf = 0; mf < 2; mf++)
#pragma unroll
        for (int f = 0; f < 8; f++)
#pragma unroll
            for (int i = 0; i < 4; i++) c[mf][f][i] = 0.f;

    for (int ch = 0; ch < 16; ch++) {
        const int kc = ch * KC;
        __syncthreads();
#pragma unroll
        for (int j = 0; j < 8; j++) {
            int it = tid + j * 256;
            int r = it >> 4;
            int kq = (it & 15) << 2;
            float4 fa = *(const float4*)(Ap + (size_t)(m0 + r) * KDIM + kc + kq);
            float4 fb = *(const float4*)(W  + (size_t)(n0 + r) * KDIM + kc + kq);
            uint4 ua = make_uint4(f2tf32(fa.x), f2tf32(fa.y), f2tf32(fa.z), f2tf32(fa.w));
            uint4 ub = make_uint4(f2tf32(fb.x), f2tf32(fb.y), f2tf32(fb.z), f2tf32(fb.w));
            *(uint4*)(As + r * PITCH + kq) = ua;
            *(uint4*)(Bs + r * PITCH + kq) = ub;
        }
        __syncthreads();

#pragma unroll
        for (int ks = 0; ks < 8; ks++) {
            const int kk = ks * 8;
            uint32_t a[2][4];
#pragma unroll
            for (int mf = 0; mf < 2; mf++) {
                int row = wm * 32 + mf * 16 + g;
                a[mf][0] = As[row * PITCH + kk + t];
                a[mf][1] = As[(row + 8) * PITCH + kk + t];
                a[mf][2] = As[row * PITCH + kk + t + 4];
                a[mf][3] = As[(row + 8) * PITCH + kk + t + 4];
            }
#pragma unroll
            for (int f = 0; f < 8; f++) {
                int n = wn * 64 + f * 8 + g;
                uint32_t b0 = Bs[n * PITCH + kk + t];
                uint32_t b1 = Bs[n * PITCH + kk + t + 4];
                mma_tf32(c[0][f], a[0], b0, b1);
                mma_tf32(c[1][f], a[1], b0, b1);
            }
        }
    }

#pragma unroll
    for (int mf = 0; mf < 2; mf++) {
#pragma unroll
        for (int f = 0; f < 8; f++) {
            const float* cc = c[mf][f];
            const int col = n0 + wn * 64 + f * 8 + 2 * t;
            const int rbase = m0 + wm * 32 + mf * 16 + g;
#pragma unroll
            for (int half = 0; half < 2; half++) {
                const int m = rbase + half * 8;
                const float v1 = cc[half * 2], v2 = cc[half * 2 + 1];
                if (mode == 3) {
                    *(float2*)(Cout + (size_t)m * NDIM + col) = make_float2(v1, v2);
                } else {
                    const int b = m >> 11, s = m & 2047;
                    const int h = col >> 6, d = col & 63;   // d even
                    const size_t base =
                        ((size_t)(b * NHEADS + h) * SEQ + s) * HDIM + d;
                    if (mode == 2) {
                        *(float2*)(g_v + base) = make_float2(v1, v2);
                    } else {
                        const float cs = g_cos[s * 32 + (d >> 1)];
                        const float sn = g_sin[s * 32 + (d >> 1)];
                        float* dst = mode ? g_k : g_q;
                        *(float2*)(dst + base) =
                            make_float2(v1 * cs - v2 * sn, v1 * sn + v2 * cs);
                    }
                }
            }
        }
    }
}

// ---------------------------------------------------------------------------
// Causal flash attention on tensor cores: tf32 mma.sync with 3-product hi/lo
// split (error ~2^-22 -> negligible vs fp32). Br=Bc=64, 128 threads (4 warps
// x 16 Q-rows). Q,K,V split hi/lo in smem (pitch 68: QK frag reads conflict-
// free). P is rerouted C-layout -> A-layout via shfl (no smem staging).
// ---------------------------------------------------------------------------
#define AP 68
#define TSZ (64 * AP)
#define ATTN_SMEM (6 * TSZ * 4)     // Qh Ql Kh Kl Vh Vl = 104448 bytes

__global__ __launch_bounds__(128)
void flash_tc() {
    extern __shared__ __align__(16) uint32_t sm[];
    uint32_t* Qh = sm;
    uint32_t* Ql = sm + TSZ;
    uint32_t* Kh = sm + 2 * TSZ;
    uint32_t* Kl = sm + 3 * TSZ;
    uint32_t* Vh = sm + 4 * TSZ;
    uint32_t* Vl = sm + 5 * TSZ;

    const int qt = blockIdx.x;
    const int bh = blockIdx.y;
    const int tid = threadIdx.x;
    const int warp = tid >> 5, lane = tid & 31;
    const int g = lane >> 2, t = lane & 3;
    const int wr = warp * 16;                 // warp's Q-row base (local)

    // ---- load Q tile (scale 1/8 folded in), split hi/lo ----
    const float* Qg = g_q + ((size_t)bh * SEQ + qt * 64) * HDIM;
#pragma unroll
    for (int j = 0; j < 8; j++) {
        int it = tid + j * 128;
        int r = it >> 4, c0 = (it & 15) * 4;
        float4 f = *(const float4*)(Qg + r * 64 + c0);
        float v[4] = {f.x * 0.125f, f.y * 0.125f, f.z * 0.125f, f.w * 0.125f};
        uint32_t h[4], l[4];
#pragma unroll
        for (int i = 0; i < 4; i++) {
            h[i] = f2tf32(v[i]);
            l[i] = f2tf32(v[i] - __uint_as_float(h[i]));
        }
        *(uint4*)(Qh + r * AP + c0) = make_uint4(h[0], h[1], h[2], h[3]);
        *(uint4*)(Ql + r * AP + c0) = make_uint4(l[0], l[1], l[2], l[3]);
    }

    float m_i[2] = {-1e30f, -1e30f};
    float l_i[2] = {0.f, 0.f};
    float o[8][4];
#pragma unroll
    for (int j = 0; j < 8; j++)
#pragma unroll
        for (int i = 0; i < 4; i++) o[j][i] = 0.f;

    for (int kt = 0; kt <= qt; kt++) {
        __syncthreads();   // previous iteration's MMAs done before overwrite
        const float* Kg = g_k + ((size_t)bh * SEQ + kt * 64) * HDIM;
        const float* Vg = g_v + ((size_t)bh * SEQ + kt * 64) * HDIM;
#pragma unroll
        for (int j = 0; j < 8; j++) {
            int it = tid + j * 128;
            int r = it >> 4, c0 = (it & 15) * 4;
            float4 fk = *(const float4*)(Kg + r * 64 + c0);
            float4 fv = *(const float4*)(Vg + r * 64 + c0);
            float kv[4] = {fk.x, fk.y, fk.z, fk.w};
            float vv[4] = {fv.x, fv.y, fv.z, fv.w};
            uint32_t kh[4], kl[4], vh[4], vl[4];
#pragma unroll
            for (int i = 0; i < 4; i++) {
                kh[i] = f2tf32(kv[i]);
                kl[i] = f2tf32(kv[i] - __uint_as_float(kh[i]));
                vh[i] = f2tf32(vv[i]);
                vl[i] = f2tf32(vv[i] - __uint_as_float(vh[i]));
            }
            *(uint4*)(Kh + r * AP + c0) = make_uint4(kh[0], kh[1], kh[2], kh[3]);
            *(uint4*)(Kl + r * AP + c0) = make_uint4(kl[0], kl[1], kl[2], kl[3]);
            *(uint4*)(Vh + r * AP + c0) = make_uint4(vh[0], vh[1], vh[2], vh[3]);
            *(uint4*)(Vl + r * AP + c0) = make_uint4(vl[0], vl[1], vl[2], vl[3]);
        }
        __syncthreads();

        // ---- S = Q K^T (split: hh + hl + lh) ----
        float c[8][4];
#pragma unroll
        for (int j = 0; j < 8; j++)
#pragma unroll
            for (int i = 0; i < 4; i++) c[j][i] = 0.f;

#pragma unroll
        for (int k0 = 0; k0 < 8; k0++) {
            const int kk = k0 * 8;
            uint32_t ah[4], al[4];
            ah[0] = Qh[(wr + g) * AP + kk + t];
            ah[1] = Qh[(wr + g + 8) * AP + kk + t];
            ah[2] = Qh[(wr + g) * AP + kk + t + 4];
            ah[3] = Qh[(wr + g + 8) * AP + kk + t + 4];
            al[0] = Ql[(wr + g) * AP + kk + t];
            al[1] = Ql[(wr + g + 8) * AP + kk + t];
            al[2] = Ql[(wr + g) * AP + kk + t + 4];
            al[3] = Ql[(wr + g + 8) * AP + kk + t + 4];
#pragma unroll
            for (int j = 0; j < 8; j++) {
                const int n = j * 8 + g;
                uint32_t bh0 = Kh[n * AP + kk + t];
                uint32_t bh1 = Kh[n * AP + kk + t + 4];
                uint32_t bl0 = Kl[n * AP + kk + t];
                uint32_t bl1 = Kl[n * AP + kk + t + 4];
                mma_tf32(c[j], ah, bh0, bh1);
                mma_tf32(c[j], ah, bl0, bl1);
                mma_tf32(c[j], al, bh0, bh1);
            }
        }

        // ---- causal mask (diagonal tile only; local indices aligned) ----
        if (kt == qt) {
#pragma unroll
            for (int j = 0; j < 8; j++) {
                const int col0 = j * 8 + 2 * t;
                const int r0 = wr + g, r1 = wr + g + 8;
                if (col0 > r0)     c[j][0] = -1e30f;
                if (col0 + 1 > r0) c[j][1] = -1e30f;
                if (col0 > r1)     c[j][2] = -1e30f;
                if (col0 + 1 > r1) c[j][3] = -1e30f;
            }
        }

        // ---- online softmax (rows g and g+8 of this warp) ----
        float mx0 = -1e30f, mx1 = -1e30f;
#pragma unroll
        for (int j = 0; j < 8; j++) {
            mx0 = fmaxf(mx0, fmaxf(c[j][0], c[j][1]));
            mx1 = fmaxf(mx1, fmaxf(c[j][2], c[j][3]));
        }
#pragma unroll
        for (int off = 1; off < 4; off <<= 1) {
            mx0 = fmaxf(mx0, __shfl_xor_sync(0xffffffffu, mx0, off));
            mx1 = fmaxf(mx1, __shfl_xor_sync(0xffffffffu, mx1, off));
        }
        const float mn0 = fmaxf(m_i[0], mx0);
        const float mn1 = fmaxf(m_i[1], mx1);
        const float al0 = __expf(m_i[0] - mn0);
        const float al1 = __expf(m_i[1] - mn1);
        float sum0 = 0.f, sum1 = 0.f;
#pragma unroll
        for (int j = 0; j < 8; j++) {
            c[j][0] = __expf(c[j][0] - mn0);
            c[j][1] = __expf(c[j][1] - mn0);
            c[j][2] = __expf(c[j][2] - mn1);
            c[j][3] = __expf(c[j][3] - mn1);
            sum0 += c[j][0] + c[j][1];
            sum1 += c[j][2] + c[j][3];
        }
#pragma unroll
        for (int off = 1; off < 4; off <<= 1) {
            sum0 += __shfl_xor_sync(0xffffffffu, sum0, off);
            sum1 += __shfl_xor_sync(0xffffffffu, sum1, off);
        }
        l_i[0] = l_i[0] * al0 + sum0;
        l_i[1] = l_i[1] * al1 + sum1;
        m_i[0] = mn0; m_i[1] = mn1;
#pragma unroll
        for (int j = 0; j < 8; j++) {
            o[j][0] *= al0; o[j][1] *= al0;
            o[j][2] *= al1; o[j][3] *= al1;
        }

        // ---- O += P V : reroute P (C-layout) -> A-frags via shfl ----
#pragma unroll
        for (int k0 = 0; k0 < 8; k0++) {
            const int src0 = g * 4 + (t >> 1);       // col k0*8 + t
            const int src1 = src0 + 2;               // col k0*8 + t + 4
            const int e = t & 1;
            float p0a = __shfl_sync(0xffffffffu, c[k0][0], src0);
            float p0b = __shfl_sync(0xffffffffu, c[k0][1], src0);
            float p1a = __shfl_sync(0xffffffffu, c[k0][2], src0);
            float p1b = __shfl_sync(0xffffffffu, c[k0][3], src0);
            float p2a = __shfl_sync(0xffffffffu, c[k0][0], src1);
            float p2b = __shfl_sync(0xffffffffu, c[k0][1], src1);
            float p3a = __shfl_sync(0xffffffffu, c[k0][2], src1);
            float p3b = __shfl_sync(0xffffffffu, c[k0][3], src1);
            float a0 = e ? p0b : p0a;
            float a1 = e ? p1b : p1a;
            float a2 = e ? p2b : p2a;
            float a3 = e ? p3b : p3a;
            uint32_t ph[4], pl[4];
            ph[0] = f2tf32(a0); pl[0] = f2tf32(a0 - __uint_as_float(ph[0]));
            ph[1] = f2tf32(a1); pl[1] = f2tf32(a1 - __uint_as_float(ph[1]));
            ph[2] = f2tf32(a2); pl[2] = f2tf32(a2 - __uint_as_float(ph[2]));
            ph[3] = f2tf32(a3); pl[3] = f2tf32(a3 - __uint_as_float(ph[3]));
            const int kr0 = k0 * 8 + t, kr1 = k0 * 8 + t + 4;
#pragma unroll
            for (int j = 0; j < 8; j++) {
                const int n = j * 8 + g;
                uint32_t bh0 = Vh[kr0 * AP + n];
                uint32_t bh1 = Vh[kr1 * AP + n];
                uint32_t bl0 = Vl[kr0 * AP + n];
                uint32_t bl1 = Vl[kr1 * AP + n];
                mma_tf32(o[j], ph, bh0, bh1);
                mma_tf32(o[j], ph, bl0, bl1);
                mma_tf32(o[j], pl, bh0, bh1);
            }
        }
    }

    // ---- epilogue: O / l -> g_o [b, s, h*64 + d] ----
    const int b = bh >> 4, h = bh & 15;
    const float inv0 = 1.f / l_i[0];
    const float inv1 = 1.f / l_i[1];
    const int s0 = qt * 64 + wr + g;
    const int s1 = s0 + 8;
    float* row0 = g_o + ((size_t)b * SEQ + s0) * DMODEL + h * HDIM;
    float* row1 = g_o + ((size_t)b * SEQ + s1) * DMODEL + h * HDIM;
#pragma unroll
    for (int j = 0; j < 8; j++) {
        const int d = j * 8 + 2 * t;
        *(float2*)(row0 + d) = make_float2(o[j][0] * inv0, o[j][1] * inv0);
        *(float2*)(row1 + d) = make_float2(o[j][2] * inv1, o[j][3] * inv1);
    }
}

// ---------------------------------------------------------------------------
extern "C" void kernel_launch(void* const* d_in, const int* in_sizes, int n_in,
                              void* d_out, int out_size) {
    const float* x  = (const float*)d_in[0];
    const float* Wq = (const float*)d_in[1];
    const float* Wk = (const float*)d_in[2];
    const float* Wv = (const float*)d_in[3];
    const float* Wo = (const float*)d_in[4];
    const int* tpos = (const int*)d_in[5];
    float* out = (float*)d_out;

    rope_table_kernel<<<SEQ, 32>>>(tpos);

    cudaFuncSetAttribute(gemm_mma, cudaFuncAttributeMaxDynamicSharedMemorySize,
                         GEMM_SMEM);
    dim3 gqkv(NDIM / 128, MTOT / 128, 3);
    gemm_mma<<<gqkv, 256, GEMM_SMEM>>>(x, Wq, Wk, Wv, nullptr);

    cudaFuncSetAttribute(flash_tc, cudaFuncAttributeMaxDynamicSharedMemorySize,
                         ATTN_SMEM);
    flash_tc<<<dim3(SEQ / 64, BATCH * NHEADS), 128, ATTN_SMEM>>>();

    dim3 gp(NDIM / 128, MTOT / 128, 1);
    gemm_mma<<<gp, 256, GEMM_SMEM>>>(nullptr, Wo, nullptr, nullptr, out);
}

// round 8
// speedup vs baseline: 3.3825x; 1.3574x over previous
#include <cuda_runtime.h>
#include <cuda_bf16.h>
#include <math.h>
#include <stdint.h>

// Shapes fixed: B=4, S=2048, D=1024, H=16, dh=64.
#define BATCH     4
#define SEQ       2048
#define DMODEL    1024
#define NHEADS    16
#define HDIM      64
#define MTOT      (BATCH * SEQ)      // 8192
#define KDIM      DMODEL
#define NDIM      DMODEL
#define QKV_ELEMS (BATCH * NHEADS * SEQ * HDIM)   // 8388608

// Scratch: 6 x 16 MiB bf16 + 32 MiB fp32 + tables = 128.5 MiB total
// (same footprint as the round-5 kernel that passed the allocation guard).
__device__ __nv_bfloat16 g_qh[QKV_ELEMS];   // Q hi/lo: scaled 1/8, RoPE'd, [b,h,s,d]
__device__ __nv_bfloat16 g_ql[QKV_ELEMS];
__device__ __nv_bfloat16 g_kh[QKV_ELEMS];   // K hi/lo: RoPE'd, [b,h,s,d]
__device__ __nv_bfloat16 g_kl[QKV_ELEMS];
__device__ __nv_bfloat16 g_vh[QKV_ELEMS];   // V hi/lo TRANSPOSED: [b,h,d,s]
__device__ __nv_bfloat16 g_vl[QKV_ELEMS];
__device__ float         g_o [BATCH * SEQ * DMODEL];
__device__ float         g_cos[SEQ * (HDIM / 2)];
__device__ float         g_sin[SEQ * (HDIM / 2)];

// ---------------------------------------------------------------------------
// helpers
// ---------------------------------------------------------------------------
__device__ __forceinline__ uint32_t f2tf32(float x) {
    uint32_t u;
    asm("cvt.rna.tf32.f32 %0, %1;" : "=r"(u) : "f"(x));
    return u;
}
__device__ __forceinline__ void mma_tf32(float c[4], const uint32_t a[4],
                                         uint32_t b0, uint32_t b1) {
    asm volatile(
        "mma.sync.aligned.m16n8k8.row.col.f32.tf32.tf32.f32 "
        "{%0,%1,%2,%3}, {%4,%5,%6,%7}, {%8,%9}, {%0,%1,%2,%3};"
        : "+f"(c[0]), "+f"(c[1]), "+f"(c[2]), "+f"(c[3])
        : "r"(a[0]), "r"(a[1]), "r"(a[2]), "r"(a[3]), "r"(b0), "r"(b1));
}
__device__ __forceinline__ void mma_bf16(float c[4], const uint32_t a[4],
                                         uint32_t b0, uint32_t b1) {
    asm volatile(
        "mma.sync.aligned.m16n8k16.row.col.f32.bf16.bf16.f32 "
        "{%0,%1,%2,%3}, {%4,%5,%6,%7}, {%8,%9}, {%0,%1,%2,%3};"
        : "+f"(c[0]), "+f"(c[1]), "+f"(c[2]), "+f"(c[3])
        : "r"(a[0]), "r"(a[1]), "r"(a[2]), "r"(a[3]), "r"(b0), "r"(b1));
}
// pack two fp32 -> bf16x2; first operand lands in the HIGH half.
__device__ __forceinline__ uint32_t packbf(float hi, float lo) {
    uint32_t r;
    asm("cvt.rn.bf16x2.f32 %0, %1, %2;" : "=r"(r) : "f"(hi), "f"(lo));
    return r;
}

// ---------------------------------------------------------------------------
// RoPE table
// ---------------------------------------------------------------------------
__global__ void rope_table_kernel(const int* __restrict__ tpos) {
    int s = blockIdx.x;
    int f = threadIdx.x;
    double inv = exp(-(2.0 * (double)f / (double)HDIM) * log(10000.0));
    double a = (double)tpos[s] * inv;
    g_cos[s * 32 + f] = (float)cos(a);
    g_sin[s * 32 + f] = (float)sin(a);
}

// ---------------------------------------------------------------------------
// tf32 mma.sync GEMM (round-4/5 proven core): C[m][n]=sum_k A[m][k]*W[n][k].
// CTA 128x128, 8 warps (4m x 2n), K-chunks of 64, pitch 68. In-fill cvt.
// Epilogues:
//  mode 0: Q -> RoPE, *0.125, bf16 hi/lo split -> g_qh/g_ql [b,h,s,d]
//  mode 1: K -> RoPE,          bf16 hi/lo split -> g_kh/g_kl [b,h,s,d]
//  mode 2: V ->                bf16 hi/lo split -> g_vh/g_vl TRANSPOSED [b,h,d,s]
//  mode 3: plain fp32 store to Cout (A = g_o).
// ---------------------------------------------------------------------------
#define KC      64
#define PITCH   68
#define GEMM_SMEM (2 * 128 * PITCH * 4)   // 69632 bytes

__global__ __launch_bounds__(256)
void gemm_mma(const float* __restrict__ A,
              const float* __restrict__ W0, const float* __restrict__ W1,
              const float* __restrict__ W2,
              float* __restrict__ Cout) {
    extern __shared__ __align__(16) uint32_t smu[];
    uint32_t* As = smu;
    uint32_t* Bs = smu + 128 * PITCH;

    const int mode = Cout ? 3 : blockIdx.z;
    const float* W = (mode == 1) ? W1 : (mode == 2) ? W2 : W0;
    const float* Ap = A ? A : g_o;

    const int tid = threadIdx.x;
    const int warp = tid >> 5, lane = tid & 31;
    const int wm = warp >> 1, wn = warp & 1;
    const int g = lane >> 2, t = lane & 3;
    const int m0 = blockIdx.y * 128, n0 = blockIdx.x * 128;

    float c[2][8][4];
#pragma unroll
    for (int mf = 0; mf < 2; mf++)
#pragma unroll
        for (int f = 0; f < 8; f++)
#pragma unroll
            for (int i = 0; i < 4; i++) c[mf][f][i] = 0.f;

    for (int ch = 0; ch < 16; ch++) {
        const int kc = ch * KC;
        __syncthreads();
#pragma unroll
        for (int j = 0; j < 8; j++) {
            int it = tid + j * 256;
            int r = it >> 4;
            int kq = (it & 15) << 2;
            float4 fa = *(const float4*)(Ap + (size_t)(m0 + r) * KDIM + kc + kq);
            float4 fb = *(const float4*)(W  + (size_t)(n0 + r) * KDIM + kc + kq);
            uint4 ua = make_uint4(f2tf32(fa.x), f2tf32(fa.y), f2tf32(fa.z), f2tf32(fa.w));
            uint4 ub = make_uint4(f2tf32(fb.x), f2tf32(fb.y), f2tf32(fb.z), f2tf32(fb.w));
            *(uint4*)(As + r * PITCH + kq) = ua;
            *(uint4*)(Bs + r * PITCH + kq) = ub;
        }
        __syncthreads();

#pragma unroll
        for (int ks = 0; ks < 8; ks++) {
            const int kk = ks * 8;
            uint32_t a[2][4];
#pragma unroll
            for (int mf = 0; mf < 2; mf++) {
                int row = wm * 32 + mf * 16 + g;
                a[mf][0] = As[row * PITCH + kk + t];
                a[mf][1] = As[(row + 8) * PITCH + kk + t];
                a[mf][2] = As[row * PITCH + kk + t + 4];
                a[mf][3] = As[(row + 8) * PITCH + kk + t + 4];
            }
#pragma unroll
            for (int f = 0; f < 8; f++) {
                int n = wn * 64 + f * 8 + g;
                uint32_t b0 = Bs[n * PITCH + kk + t];
                uint32_t b1 = Bs[n * PITCH + kk + t + 4];
                mma_tf32(c[0][f], a[0], b0, b1);
                mma_tf32(c[1][f], a[1], b0, b1);
            }
        }
    }

    // Epilogue. c[mf][f]: rows (g, g+8), cols (2t, 2t+1) — RoPE pairs.
#pragma unroll
    for (int mf = 0; mf < 2; mf++) {
#pragma unroll
        for (int f = 0; f < 8; f++) {
            const float* cc = c[mf][f];
            const int col = n0 + wn * 64 + f * 8 + 2 * t;
            const int rbase = m0 + wm * 32 + mf * 16 + g;
#pragma unroll
            for (int half = 0; half < 2; half++) {
                const int m = rbase + half * 8;
                float v1 = cc[half * 2], v2 = cc[half * 2 + 1];
                if (mode == 3) {
                    *(float2*)(Cout + (size_t)m * NDIM + col) = make_float2(v1, v2);
                } else {
                    const int b = m >> 11, s = m & 2047;
                    const int h = col >> 6, d = col & 63;   // d even
                    if (mode < 2) {     // RoPE for Q and K
                        const float cs = g_cos[s * 32 + (d >> 1)];
                        const float sn = g_sin[s * 32 + (d >> 1)];
                        float r1 = v1 * cs - v2 * sn;
                        float r2 = v1 * sn + v2 * cs;
                        if (mode == 0) { r1 *= 0.125f; r2 *= 0.125f; }
                        v1 = r1; v2 = r2;
                    }
                    __nv_bfloat16 h1 = __float2bfloat16(v1);
                    __nv_bfloat16 h2 = __float2bfloat16(v2);
                    __nv_bfloat16 l1 = __float2bfloat16(v1 - __bfloat162float(h1));
                    __nv_bfloat16 l2 = __float2bfloat16(v2 - __bfloat162float(h2));
                    if (mode == 2) {    // V transposed: [b,h,d,s]
                        const size_t vb =
                            ((size_t)(b * NHEADS + h) * HDIM + d) * SEQ + s;
                        g_vh[vb] = h1;       g_vl[vb] = l1;
                        g_vh[vb + SEQ] = h2; g_vl[vb + SEQ] = l2;
                    } else {            // Q/K: [b,h,s,d], pair = one u32
                        const size_t base =
                            ((size_t)(b * NHEADS + h) * SEQ + s) * HDIM + d;
                        uint32_t hp = ((uint32_t)__bfloat16_as_ushort(h2) << 16)
                                    | __bfloat16_as_ushort(h1);
                        uint32_t lp = ((uint32_t)__bfloat16_as_ushort(l2) << 16)
                                    | __bfloat16_as_ushort(l1);
                        if (mode == 0) {
                            *(uint32_t*)(g_qh + base) = hp;
                            *(uint32_t*)(g_ql + base) = lp;
                        } else {
                            *(uint32_t*)(g_kh + base) = hp;
                            *(uint32_t*)(g_kl + base) = lp;
                        }
                    }
                }
            }
        }
    }
}

// ---------------------------------------------------------------------------
// Causal flash attention: bf16 m16n8k16 mma with 3-product hi/lo split.
// Br=Bc=64, 128 threads (4 warps x 16 Q-rows). Q frags live in registers
// (loaded once from pre-split gmem); K/V tiles are plain bf16 copies (zero
// cvt in the loop). P C-frags feed PV A-frags of the SAME thread (no shfl).
// smem: Kh,Kl,Vh,Vl @ 64 x 72 bf16 (pitch 36 u32, conflict-free frag reads).
// ---------------------------------------------------------------------------
#define KP 36                        // u32 pitch
#define KTSZ (64 * KP)               // 2304 u32 per tile
#define ATTN_SMEM (4 * KTSZ * 4)     // 36864 bytes

__global__ __launch_bounds__(128)
void flash_bf16() {
    extern __shared__ __align__(16) uint32_t sm[];
    uint32_t* Khs = sm;
    uint32_t* Kls = sm + KTSZ;
    uint32_t* Vhs = sm + 2 * KTSZ;
    uint32_t* Vls = sm + 3 * KTSZ;

    const int qt = gridDim.x - 1 - (int)blockIdx.x;   // heavy tiles first
    const int bh = blockIdx.y;
    const int tid = threadIdx.x;
    const int warp = tid >> 5, lane = tid & 31;
    const int g = lane >> 2, t = lane & 3;
    const int wr = warp * 16;

    // ---- Q fragments -> registers (u32 = bf16x2, k-pairs 2t,2t+1) ----
    const uint32_t* Qhg = (const uint32_t*)g_qh;
    const uint32_t* Qlg = (const uint32_t*)g_ql;
    const size_t qrow0 = (((size_t)bh * SEQ + qt * 64 + wr + g) * HDIM) >> 1;
    const size_t qrow1 = qrow0 + (8 * HDIM >> 1);
    uint32_t qh[4][4], ql[4][4];
#pragma unroll
    for (int k0 = 0; k0 < 4; k0++) {
        const int o8 = 8 * k0 + t;
        qh[k0][0] = Qhg[qrow0 + o8];     ql[k0][0] = Qlg[qrow0 + o8];
        qh[k0][1] = Qhg[qrow1 + o8];     ql[k0][1] = Qlg[qrow1 + o8];
        qh[k0][2] = Qhg[qrow0 + o8 + 4]; ql[k0][2] = Qlg[qrow0 + o8 + 4];
        qh[k0][3] = Qhg[qrow1 + o8 + 4]; ql[k0][3] = Qlg[qrow1 + o8 + 4];
    }

    float m_i[2] = {-1e30f, -1e30f};
    float l_i[2] = {0.f, 0.f};
    float o[8][4];
#pragma unroll
    for (int j = 0; j < 8; j++)
#pragma unroll
        for (int i = 0; i < 4; i++) o[j][i] = 0.f;

    const uint32_t* Khg = (const uint32_t*)g_kh;
    const uint32_t* Klg = (const uint32_t*)g_kl;
    const uint32_t* Vhg = (const uint32_t*)g_vh;
    const uint32_t* Vlg = (const uint32_t*)g_vl;

    for (int kt = 0; kt <= qt; kt++) {
        __syncthreads();   // previous iteration's MMAs done before overwrite
        // K tile: rows = seq, cols = hd. V tile (transposed gmem): rows = hd,
        // cols = seq. Both 64x64 bf16 = 64 rows x 32 u32; uint4 copies.
        const size_t kbase = (((size_t)bh * SEQ + kt * 64) * HDIM) >> 1;
        const size_t vbase = (((size_t)bh * HDIM) * SEQ + kt * 64) >> 1;
#pragma unroll
        for (int j = 0; j < 4; j++) {
            int it = tid + j * 128;
            int r = it >> 3;
            int cu = (it & 7) * 4;                 // u32 offset within row
            const size_t ks = kbase + r * 32 + cu; // K row stride 32 u32
            const size_t vs = vbase + (size_t)r * (SEQ / 2) + cu;
            *(uint4*)(Khs + r * KP + cu) = *(const uint4*)(Khg + ks);
            *(uint4*)(Kls + r * KP + cu) = *(const uint4*)(Klg + ks);
            *(uint4*)(Vhs + r * KP + cu) = *(const uint4*)(Vhg + vs);
            *(uint4*)(Vls + r * KP + cu) = *(const uint4*)(Vlg + vs);
        }
        __syncthreads();

        // ---- S = Q K^T (hh + hl + lh), 4 k-steps of 16 ----
        float c[8][4];
#pragma unroll
        for (int j = 0; j < 8; j++)
#pragma unroll
            for (int i = 0; i < 4; i++) c[j][i] = 0.f;

#pragma unroll
        for (int k0 = 0; k0 < 4; k0++) {
            const int o8 = 8 * k0 + t;
#pragma unroll
            for (int j = 0; j < 8; j++) {
                const int n = j * 8 + g;
                uint32_t bh0 = Khs[n * KP + o8];
                uint32_t bh1 = Khs[n * KP + o8 + 4];
                uint32_t bl0 = Kls[n * KP + o8];
                uint32_t bl1 = Kls[n * KP + o8 + 4];
                mma_bf16(c[j], qh[k0], bh0, bh1);
                mma_bf16(c[j], qh[k0], bl0, bl1);
                mma_bf16(c[j], ql[k0], bh0, bh1);
            }
        }

        // ---- causal mask (diagonal tile only) ----
        if (kt == qt) {
#pragma unroll
            for (int j = 0; j < 8; j++) {
                const int col0 = j * 8 + 2 * t;
                const int r0 = wr + g, r1 = wr + g + 8;
                if (col0 > r0)     c[j][0] = -1e30f;
                if (col0 + 1 > r0) c[j][1] = -1e30f;
                if (col0 > r1)     c[j][2] = -1e30f;
                if (col0 + 1 > r1) c[j][3] = -1e30f;
            }
        }

        // ---- online softmax (rows g and g+8) ----
        float mx0 = -1e30f, mx1 = -1e30f;
#pragma unroll
        for (int j = 0; j < 8; j++) {
            mx0 = fmaxf(mx0, fmaxf(c[j][0], c[j][1]));
            mx1 = fmaxf(mx1, fmaxf(c[j][2], c[j][3]));
        }
#pragma unroll
        for (int off = 1; off < 4; off <<= 1) {
            mx0 = fmaxf(mx0, __shfl_xor_sync(0xffffffffu, mx0, off));
            mx1 = fmaxf(mx1, __shfl_xor_sync(0xffffffffu, mx1, off));
        }
        const float mn0 = fmaxf(m_i[0], mx0);
        const float mn1 = fmaxf(m_i[1], mx1);
        const float al0 = __expf(m_i[0] - mn0);
        const float al1 = __expf(m_i[1] - mn1);
        float sum0 = 0.f, sum1 = 0.f;
#pragma unroll
        for (int j = 0; j < 8; j++) {
            c[j][0] = __expf(c[j][0] - mn0);
            c[j][1] = __expf(c[j][1] - mn0);
            c[j][2] = __expf(c[j][2] - mn1);
            c[j][3] = __expf(c[j][3] - mn1);
            sum0 += c[j][0] + c[j][1];
            sum1 += c[j][2] + c[j][3];
        }
#pragma unroll
        for (int off = 1; off < 4; off <<= 1) {
            sum0 += __shfl_xor_sync(0xffffffffu, sum0, off);
            sum1 += __shfl_xor_sync(0xffffffffu, sum1, off);
        }
        l_i[0] = l_i[0] * al0 + sum0;
        l_i[1] = l_i[1] * al1 + sum1;
        m_i[0] = mn0; m_i[1] = mn1;
#pragma unroll
        for (int j = 0; j < 8; j++) {
            o[j][0] *= al0; o[j][1] *= al0;
            o[j][2] *= al1; o[j][3] *= al1;
        }

        // ---- O += P V. bf16 k16 A-frag == this thread's C-frag cols. ----
#pragma unroll
        for (int k0 = 0; k0 < 4; k0++) {
            const int j0 = 2 * k0, j1 = 2 * k0 + 1;
            uint32_t ph[4], pl[4];
            ph[0] = packbf(c[j0][1], c[j0][0]);
            ph[1] = packbf(c[j0][3], c[j0][2]);
            ph[2] = packbf(c[j1][1], c[j1][0]);
            ph[3] = packbf(c[j1][3], c[j1][2]);
#pragma unroll
            for (int i = 0; i < 4; i++) {
                const int jj = (i < 2) ? j0 : j1;
                const int bb = (i & 1) * 2;
                float h0 = __uint_as_float(ph[i] << 16);
                float h1 = __uint_as_float(ph[i] & 0xFFFF0000u);
                pl[i] = packbf(c[jj][bb + 1] - h1, c[jj][bb] - h0);
            }
            const int o8 = 8 * k0 + t;
#pragma unroll
            for (int j = 0; j < 8; j++) {
                const int n = j * 8 + g;
                uint32_t vh0 = Vhs[n * KP + o8];
                uint32_t vh1 = Vhs[n * KP + o8 + 4];
                uint32_t vl0 = Vls[n * KP + o8];
                uint32_t vl1 = Vls[n * KP + o8 + 4];
                mma_bf16(o[j], ph, vh0, vh1);
                mma_bf16(o[j], ph, vl0, vl1);
                mma_bf16(o[j], pl, vh0, vh1);
            }
        }
    }

    // ---- epilogue: O / l -> g_o [b, s, h*64 + d] ----
    const int b = bh >> 4, h = bh & 15;
    const float inv0 = 1.f / l_i[0];
    const float inv1 = 1.f / l_i[1];
    const int s0 = qt * 64 + wr + g;
    const int s1 = s0 + 8;
    float* row0 = g_o + ((size_t)b * SEQ + s0) * DMODEL + h * HDIM;
    float* row1 = g_o + ((size_t)b * SEQ + s1) * DMODEL + h * HDIM;
#pragma unroll
    for (int j = 0; j < 8; j++) {
        const int d = j * 8 + 2 * t;
        *(float2*)(row0 + d) = make_float2(o[j][0] * inv0, o[j][1] * inv0);
        *(float2*)(row1 + d) = make_float2(o[j][2] * inv1, o[j][3] * inv1);
    }
}

// ---------------------------------------------------------------------------
extern "C" void kernel_launch(void* const* d_in, const int* in_sizes, int n_in,
                              void* d_out, int out_size) {
    const float* x  = (const float*)d_in[0];
    const float* Wq = (const float*)d_in[1];
    const float* Wk = (const float*)d_in[2];
    const float* Wv = (const float*)d_in[3];
    const float* Wo = (const float*)d_in[4];
    const int* tpos = (const int*)d_in[5];
    float* out = (float*)d_out;

    rope_table_kernel<<<SEQ, 32>>>(tpos);

    cudaFuncSetAttribute(gemm_mma, cudaFuncAttributeMaxDynamicSharedMemorySize,
                         GEMM_SMEM);
    dim3 gqkv(NDIM / 128, MTOT / 128, 3);
    gemm_mma<<<gqkv, 256, GEMM_SMEM>>>(x, Wq, Wk, Wv, nullptr);

    flash_bf16<<<dim3(SEQ / 64, BATCH * NHEADS), 128, ATTN_SMEM>>>();

    dim3 gp(NDIM / 128, MTOT / 128, 1);
    gemm_mma<<<gp, 256, GEMM_SMEM>>>(nullptr, Wo, nullptr, nullptr, out);
}

// round 9
// speedup vs baseline: 3.5738x; 1.0566x over previous
#include <cuda_runtime.h>
#include <cuda_bf16.h>
#include <math.h>
#include <stdint.h>

// Shapes fixed: B=4, S=2048, D=1024, H=16, dh=64.
#define BATCH     4
#define SEQ       2048
#define DMODEL    1024
#define NHEADS    16
#define HDIM      64
#define MTOT      (BATCH * SEQ)      // 8192
#define KDIM      DMODEL
#define NDIM      DMODEL
#define QKV_ELEMS (BATCH * NHEADS * SEQ * HDIM)   // 8388608

// Scratch: 6 x 16 MiB bf16 + 32 MiB fp32 + tables = 128.5 MiB total
// (footprint proven safe against the allocation guard in rounds 1/4/5/8).
__device__ __nv_bfloat16 g_qh[QKV_ELEMS];   // Q hi/lo: scaled 1/8, RoPE'd, [b,h,s,d]
__device__ __nv_bfloat16 g_ql[QKV_ELEMS];
__device__ __nv_bfloat16 g_kh[QKV_ELEMS];   // K hi/lo: RoPE'd, [b,h,s,d]
__device__ __nv_bfloat16 g_kl[QKV_ELEMS];
__device__ __nv_bfloat16 g_vh[QKV_ELEMS];   // V hi/lo TRANSPOSED: [b,h,d,s]
__device__ __nv_bfloat16 g_vl[QKV_ELEMS];
__device__ float         g_o [BATCH * SEQ * DMODEL];
__device__ float         g_cos[SEQ * (HDIM / 2)];
__device__ float         g_sin[SEQ * (HDIM / 2)];

// ---------------------------------------------------------------------------
// helpers
// ---------------------------------------------------------------------------
__device__ __forceinline__ uint32_t f2tf32(float x) {
    uint32_t u;
    asm("cvt.rna.tf32.f32 %0, %1;" : "=r"(u) : "f"(x));
    return u;
}
__device__ __forceinline__ void mma_tf32(float c[4], const uint32_t a[4],
                                         uint32_t b0, uint32_t b1) {
    asm volatile(
        "mma.sync.aligned.m16n8k8.row.col.f32.tf32.tf32.f32 "
        "{%0,%1,%2,%3}, {%4,%5,%6,%7}, {%8,%9}, {%0,%1,%2,%3};"
        : "+f"(c[0]), "+f"(c[1]), "+f"(c[2]), "+f"(c[3])
        : "r"(a[0]), "r"(a[1]), "r"(a[2]), "r"(a[3]), "r"(b0), "r"(b1));
}
__device__ __forceinline__ void mma_bf16(float c[4], const uint32_t a[4],
                                         uint32_t b0, uint32_t b1) {
    asm volatile(
        "mma.sync.aligned.m16n8k16.row.col.f32.bf16.bf16.f32 "
        "{%0,%1,%2,%3}, {%4,%5,%6,%7}, {%8,%9}, {%0,%1,%2,%3};"
        : "+f"(c[0]), "+f"(c[1]), "+f"(c[2]), "+f"(c[3])
        : "r"(a[0]), "r"(a[1]), "r"(a[2]), "r"(a[3]), "r"(b0), "r"(b1));
}
// pack two fp32 -> bf16x2; first operand lands in the HIGH half.
__device__ __forceinline__ uint32_t packbf(float hi, float lo) {
    uint32_t r;
    asm("cvt.rn.bf16x2.f32 %0, %1, %2;" : "=r"(r) : "f"(hi), "f"(lo));
    return r;
}
__device__ __forceinline__ uint4 cvt4(float4 f) {
    return make_uint4(f2tf32(f.x), f2tf32(f.y), f2tf32(f.z), f2tf32(f.w));
}

// ---------------------------------------------------------------------------
// RoPE table
// ---------------------------------------------------------------------------
__global__ void rope_table_kernel(const int* __restrict__ tpos) {
    int s = blockIdx.x;
    int f = threadIdx.x;
    double inv = exp(-(2.0 * (double)f / (double)HDIM) * log(10000.0));
    double a = (double)tpos[s] * inv;
    g_cos[s * 32 + f] = (float)cos(a);
    g_sin[s * 32 + f] = (float)sin(a);
}

// ---------------------------------------------------------------------------
// tf32 mma.sync GEMM, register-double-buffered fill.
// C[m][n] = sum_k A[m][k] * W[n][k]. CTA 128x128, 8 warps (4m x 2n),
// warp tile 32x64. KC=32 chunks, single smem stage (pitch 36, conflict-free),
// next chunk's LDGs issued before the MMA phase so their latency is hidden.
// Epilogues:
//  mode 0: Q -> RoPE, *0.125, bf16 hi/lo split -> g_qh/g_ql [b,h,s,d]
//  mode 1: K -> RoPE,          bf16 hi/lo split -> g_kh/g_kl [b,h,s,d]
//  mode 2: V ->                bf16 hi/lo split -> g_vh/g_vl TRANSPOSED [b,h,d,s]
//  mode 3: plain fp32 store to Cout (A = g_o).
// ---------------------------------------------------------------------------
#define KC      32
#define PITCH   36
#define NCHUNK  (KDIM / KC)               // 32
#define GEMM_SMEM (2 * 128 * PITCH * 4)   // A + B single stage = 36864 bytes

__global__ __launch_bounds__(256, 2)
void gemm_mma(const float* __restrict__ A,
              const float* __restrict__ W0, const float* __restrict__ W1,
              const float* __restrict__ W2,
              float* __restrict__ Cout) {
    extern __shared__ __align__(16) uint32_t smu[];
    uint32_t* As = smu;                  // [128][PITCH]
    uint32_t* Bs = smu + 128 * PITCH;

    const int mode = Cout ? 3 : blockIdx.z;
    const float* W = (mode == 1) ? W1 : (mode == 2) ? W2 : W0;
    const float* Ap = A ? A : g_o;

    const int tid = threadIdx.x;
    const int warp = tid >> 5, lane = tid & 31;
    const int wm = warp >> 1, wn = warp & 1;
    const int g = lane >> 2, t = lane & 3;
    const int m0 = blockIdx.y * 128, n0 = blockIdx.x * 128;

    // fill mapping: thread covers rows r0+32j (j<4) at k-cols q0..q0+3
    const int r0 = tid >> 3, q0 = (tid & 7) * 4;
    const float* Aptr = Ap + (size_t)(m0 + r0) * KDIM + q0;
    const float* Wptr = W  + (size_t)(n0 + r0) * KDIM + q0;

    float c[2][8][4];
#pragma unroll
    for (int mf = 0; mf < 2; mf++)
#pragma unroll
        for (int f = 0; f < 8; f++)
#pragma unroll
            for (int i = 0; i < 4; i++) c[mf][f][i] = 0.f;

    float4 ra[4], rb[4];
    // prologue: chunk 0 -> regs -> smem
#pragma unroll
    for (int j = 0; j < 4; j++) {
        ra[j] = *(const float4*)(Aptr + (size_t)(32 * j) * KDIM);
        rb[j] = *(const float4*)(Wptr + (size_t)(32 * j) * KDIM);
    }
#pragma unroll
    for (int j = 0; j < 4; j++) {
        const int r = r0 + 32 * j;
        *(uint4*)(As + r * PITCH + q0) = cvt4(ra[j]);
        *(uint4*)(Bs + r * PITCH + q0) = cvt4(rb[j]);
    }
    __syncthreads();

    for (int ch = 0; ch < NCHUNK; ch++) {
        // issue next chunk's loads now; latency hides under the MMA phase
        if (ch + 1 < NCHUNK) {
            const float* An = Aptr + (ch + 1) * KC;
            const float* Wn = Wptr + (ch + 1) * KC;
#pragma unroll
            for (int j = 0; j < 4; j++) {
                ra[j] = *(const float4*)(An + (size_t)(32 * j) * KDIM);
                rb[j] = *(const float4*)(Wn + (size_t)(32 * j) * KDIM);
            }
        }

        // MMA phase on current smem contents
#pragma unroll
        for (int ks = 0; ks < 4; ks++) {
            const int kk = ks * 8;
            uint32_t a[2][4];
#pragma unroll
            for (int mf = 0; mf < 2; mf++) {
                int row = wm * 32 + mf * 16 + g;
                a[mf][0] = As[row * PITCH + kk + t];
                a[mf][1] = As[(row + 8) * PITCH + kk + t];
                a[mf][2] = As[row * PITCH + kk + t + 4];
                a[mf][3] = As[(row + 8) * PITCH + kk + t + 4];
            }
#pragma unroll
            for (int f = 0; f < 8; f++) {
                int n = wn * 64 + f * 8 + g;
                uint32_t b0 = Bs[n * PITCH + kk + t];
                uint32_t b1 = Bs[n * PITCH + kk + t + 4];
                mma_tf32(c[0][f], a[0], b0, b1);
                mma_tf32(c[1][f], a[1], b0, b1);
            }
        }
        __syncthreads();   // all warps done reading before overwrite

        if (ch + 1 < NCHUNK) {
#pragma unroll
            for (int j = 0; j < 4; j++) {
                const int r = r0 + 32 * j;
                *(uint4*)(As + r * PITCH + q0) = cvt4(ra[j]);
                *(uint4*)(Bs + r * PITCH + q0) = cvt4(rb[j]);
            }
            __syncthreads();   // stores visible before next MMA phase
        }
    }

    // Epilogue. c[mf][f]: rows (g, g+8), cols (2t, 2t+1) — RoPE pairs.
#pragma unroll
    for (int mf = 0; mf < 2; mf++) {
#pragma unroll
        for (int f = 0; f < 8; f++) {
            const float* cc = c[mf][f];
            const int col = n0 + wn * 64 + f * 8 + 2 * t;
            const int rbase = m0 + wm * 32 + mf * 16 + g;
#pragma unroll
            for (int half = 0; half < 2; half++) {
                const int m = rbase + half * 8;
                float v1 = cc[half * 2], v2 = cc[half * 2 + 1];
                if (mode == 3) {
                    *(float2*)(Cout + (size_t)m * NDIM + col) = make_float2(v1, v2);
                } else {
                    const int b = m >> 11, s = m & 2047;
                    const int h = col >> 6, d = col & 63;   // d even
                    if (mode < 2) {     // RoPE for Q and K
                        const float cs = g_cos[s * 32 + (d >> 1)];
                        const float sn = g_sin[s * 32 + (d >> 1)];
                        float r1 = v1 * cs - v2 * sn;
                        float r2 = v1 * sn + v2 * cs;
                        if (mode == 0) { r1 *= 0.125f; r2 *= 0.125f; }
                        v1 = r1; v2 = r2;
                    }
                    __nv_bfloat16 h1 = __float2bfloat16(v1);
                    __nv_bfloat16 h2 = __float2bfloat16(v2);
                    __nv_bfloat16 l1 = __float2bfloat16(v1 - __bfloat162float(h1));
                    __nv_bfloat16 l2 = __float2bfloat16(v2 - __bfloat162float(h2));
                    if (mode == 2) {    // V transposed: [b,h,d,s]
                        const size_t vb =
                            ((size_t)(b * NHEADS + h) * HDIM + d) * SEQ + s;
                        g_vh[vb] = h1;       g_vl[vb] = l1;
                        g_vh[vb + SEQ] = h2; g_vl[vb + SEQ] = l2;
                    } else {            // Q/K: [b,h,s,d], pair = one u32
                        const size_t base =
                            ((size_t)(b * NHEADS + h) * SEQ + s) * HDIM + d;
                        uint32_t hp = ((uint32_t)__bfloat16_as_ushort(h2) << 16)
                                    | __bfloat16_as_ushort(h1);
                        uint32_t lp = ((uint32_t)__bfloat16_as_ushort(l2) << 16)
                                    | __bfloat16_as_ushort(l1);
                        if (mode == 0) {
                            *(uint32_t*)(g_qh + base) = hp;
                            *(uint32_t*)(g_ql + base) = lp;
                        } else {
                            *(uint32_t*)(g_kh + base) = hp;
                            *(uint32_t*)(g_kl + base) = lp;
                        }
                    }
                }
            }
        }
    }
}

// ---------------------------------------------------------------------------
// Causal flash attention: bf16 m16n8k16 mma with 3-product hi/lo split.
// (byte-identical to the round-8 kernel that measured ~330 us)
// ---------------------------------------------------------------------------
#define KP 36                        // u32 pitch
#define KTSZ (64 * KP)               // 2304 u32 per tile
#define ATTN_SMEM (4 * KTSZ * 4)     // 36864 bytes

__global__ __launch_bounds__(128)
void flash_bf16() {
    extern __shared__ __align__(16) uint32_t sm[];
    uint32_t* Khs = sm;
    uint32_t* Kls = sm + KTSZ;
    uint32_t* Vhs = sm + 2 * KTSZ;
    uint32_t* Vls = sm + 3 * KTSZ;

    const int qt = gridDim.x - 1 - (int)blockIdx.x;   // heavy tiles first
    const int bh = blockIdx.y;
    const int tid = threadIdx.x;
    const int warp = tid >> 5, lane = tid & 31;
    const int g = lane >> 2, t = lane & 3;
    const int wr = warp * 16;

    // ---- Q fragments -> registers (u32 = bf16x2, k-pairs 2t,2t+1) ----
    const uint32_t* Qhg = (const uint32_t*)g_qh;
    const uint32_t* Qlg = (const uint32_t*)g_ql;
    const size_t qrow0 = (((size_t)bh * SEQ + qt * 64 + wr + g) * HDIM) >> 1;
    const size_t qrow1 = qrow0 + (8 * HDIM >> 1);
    uint32_t qh[4][4], ql[4][4];
#pragma unroll
    for (int k0 = 0; k0 < 4; k0++) {
        const int o8 = 8 * k0 + t;
        qh[k0][0] = Qhg[qrow0 + o8];     ql[k0][0] = Qlg[qrow0 + o8];
        qh[k0][1] = Qhg[qrow1 + o8];     ql[k0][1] = Qlg[qrow1 + o8];
        qh[k0][2] = Qhg[qrow0 + o8 + 4]; ql[k0][2] = Qlg[qrow0 + o8 + 4];
        qh[k0][3] = Qhg[qrow1 + o8 + 4]; ql[k0][3] = Qlg[qrow1 + o8 + 4];
    }

    float m_i[2] = {-1e30f, -1e30f};
    float l_i[2] = {0.f, 0.f};
    float o[8][4];
#pragma unroll
    for (int j = 0; j < 8; j++)
#pragma unroll
        for (int i = 0; i < 4; i++) o[j][i] = 0.f;

    const uint32_t* Khg = (const uint32_t*)g_kh;
    const uint32_t* Klg = (const uint32_t*)g_kl;
    const uint32_t* Vhg = (const uint32_t*)g_vh;
    const uint32_t* Vlg = (const uint32_t*)g_vl;

    for (int kt = 0; kt <= qt; kt++) {
        __syncthreads();   // previous iteration's MMAs done before overwrite
        const size_t kbase = (((size_t)bh * SEQ + kt * 64) * HDIM) >> 1;
        const size_t vbase = (((size_t)bh * HDIM) * SEQ + kt * 64) >> 1;
#pragma unroll
        for (int j = 0; j < 4; j++) {
            int it = tid + j * 128;
            int r = it >> 3;
            int cu = (it & 7) * 4;                 // u32 offset within row
            const size_t ks = kbase + r * 32 + cu; // K row stride 32 u32
            const size_t vs = vbase + (size_t)r * (SEQ / 2) + cu;
            *(uint4*)(Khs + r * KP + cu) = *(const uint4*)(Khg + ks);
            *(uint4*)(Kls + r * KP + cu) = *(const uint4*)(Klg + ks);
            *(uint4*)(Vhs + r * KP + cu) = *(const uint4*)(Vhg + vs);
            *(uint4*)(Vls + r * KP + cu) = *(const uint4*)(Vlg + vs);
        }
        __syncthreads();

        // ---- S = Q K^T (hh + hl + lh), 4 k-steps of 16 ----
        float c[8][4];
#pragma unroll
        for (int j = 0; j < 8; j++)
#pragma unroll
            for (int i = 0; i < 4; i++) c[j][i] = 0.f;

#pragma unroll
        for (int k0 = 0; k0 < 4; k0++) {
            const int o8 = 8 * k0 + t;
#pragma unroll
            for (int j = 0; j < 8; j++) {
                const int n = j * 8 + g;
                uint32_t bh0 = Khs[n * KP + o8];
                uint32_t bh1 = Khs[n * KP + o8 + 4];
                uint32_t bl0 = Kls[n * KP + o8];
                uint32_t bl1 = Kls[n * KP + o8 + 4];
                mma_bf16(c[j], qh[k0], bh0, bh1);
                mma_bf16(c[j], qh[k0], bl0, bl1);
                mma_bf16(c[j], ql[k0], bh0, bh1);
            }
        }

        // ---- causal mask (diagonal tile only) ----
        if (kt == qt) {
#pragma unroll
            for (int j = 0; j < 8; j++) {
                const int col0 = j * 8 + 2 * t;
                const int r0 = wr + g, r1 = wr + g + 8;
                if (col0 > r0)     c[j][0] = -1e30f;
                if (col0 + 1 > r0) c[j][1] = -1e30f;
                if (col0 > r1)     c[j][2] = -1e30f;
                if (col0 + 1 > r1) c[j][3] = -1e30f;
            }
        }

        // ---- online softmax (rows g and g+8) ----
        float mx0 = -1e30f, mx1 = -1e30f;
#pragma unroll
        for (int j = 0; j < 8; j++) {
            mx0 = fmaxf(mx0, fmaxf(c[j][0], c[j][1]));
            mx1 = fmaxf(mx1, fmaxf(c[j][2], c[j][3]));
        }
#pragma unroll
        for (int off = 1; off < 4; off <<= 1) {
            mx0 = fmaxf(mx0, __shfl_xor_sync(0xffffffffu, mx0, off));
            mx1 = fmaxf(mx1, __shfl_xor_sync(0xffffffffu, mx1, off));
        }
        const float mn0 = fmaxf(m_i[0], mx0);
        const float mn1 = fmaxf(m_i[1], mx1);
        const float al0 = __expf(m_i[0] - mn0);
        const float al1 = __expf(m_i[1] - mn1);
        float sum0 = 0.f, sum1 = 0.f;
#pragma unroll
        for (int j = 0; j < 8; j++) {
            c[j][0] = __expf(c[j][0] - mn0);
            c[j][1] = __expf(c[j][1] - mn0);
            c[j][2] = __expf(c[j][2] - mn1);
            c[j][3] = __expf(c[j][3] - mn1);
            sum0 += c[j][0] + c[j][1];
            sum1 += c[j][2] + c[j][3];
        }
#pragma unroll
        for (int off = 1; off < 4; off <<= 1) {
            sum0 += __shfl_xor_sync(0xffffffffu, sum0, off);
            sum1 += __shfl_xor_sync(0xffffffffu, sum1, off);
        }
        l_i[0] = l_i[0] * al0 + sum0;
        l_i[1] = l_i[1] * al1 + sum1;
        m_i[0] = mn0; m_i[1] = mn1;
#pragma unroll
        for (int j = 0; j < 8; j++) {
            o[j][0] *= al0; o[j][1] *= al0;
            o[j][2] *= al1; o[j][3] *= al1;
        }

        // ---- O += P V. bf16 k16 A-frag == this thread's C-frag cols. ----
#pragma unroll
        for (int k0 = 0; k0 < 4; k0++) {
            const int j0 = 2 * k0, j1 = 2 * k0 + 1;
            uint32_t ph[4], pl[4];
            ph[0] = packbf(c[j0][1], c[j0][0]);
            ph[1] = packbf(c[j0][3], c[j0][2]);
            ph[2] = packbf(c[j1][1], c[j1][0]);
            ph[3] = packbf(c[j1][3], c[j1][2]);
#pragma unroll
            for (int i = 0; i < 4; i++) {
                const int jj = (i < 2) ? j0 : j1;
                const int bb = (i & 1) * 2;
                float h0 = __uint_as_float(ph[i] << 16);
                float h1 = __uint_as_float(ph[i] & 0xFFFF0000u);
                pl[i] = packbf(c[jj][bb + 1] - h1, c[jj][bb] - h0);
            }
            const int o8 = 8 * k0 + t;
#pragma unroll
            for (int j = 0; j < 8; j++) {
                const int n = j * 8 + g;
                uint32_t vh0 = Vhs[n * KP + o8];
                uint32_t vh1 = Vhs[n * KP + o8 + 4];
                uint32_t vl0 = Vls[n * KP + o8];
                uint32_t vl1 = Vls[n * KP + o8 + 4];
                mma_bf16(o[j], ph, vh0, vh1);
                mma_bf16(o[j], ph, vl0, vl1);
                mma_bf16(o[j], pl, vh0, vh1);
            }
        }
    }

    // ---- epilogue: O / l -> g_o [b, s, h*64 + d] ----
    const int b = bh >> 4, h = bh & 15;
    const float inv0 = 1.f / l_i[0];
    const float inv1 = 1.f / l_i[1];
    const int s0 = qt * 64 + wr + g;
    const int s1 = s0 + 8;
    float* row0 = g_o + ((size_t)b * SEQ + s0) * DMODEL + h * HDIM;
    float* row1 = g_o + ((size_t)b * SEQ + s1) * DMODEL + h * HDIM;
#pragma unroll
    for (int j = 0; j < 8; j++) {
        const int d = j * 8 + 2 * t;
        *(float2*)(row0 + d) = make_float2(o[j][0] * inv0, o[j][1] * inv0);
        *(float2*)(row1 + d) = make_float2(o[j][2] * inv1, o[j][3] * inv1);
    }
}

// ---------------------------------------------------------------------------
extern "C" void kernel_launch(void* const* d_in, const int* in_sizes, int n_in,
                              void* d_out, int out_size) {
    const float* x  = (const float*)d_in[0];
    const float* Wq = (const float*)d_in[1];
    const float* Wk = (const float*)d_in[2];
    const float* Wv = (const float*)d_in[3];
    const float* Wo = (const float*)d_in[4];
    const int* tpos = (const int*)d_in[5];
    float* out = (float*)d_out;

    rope_table_kernel<<<SEQ, 32>>>(tpos);

    dim3 gqkv(NDIM / 128, MTOT / 128, 3);
    gemm_mma<<<gqkv, 256, GEMM_SMEM>>>(x, Wq, Wk, Wv, nullptr);

    flash_bf16<<<dim3(SEQ / 64, BATCH * NHEADS), 128, ATTN_SMEM>>>();

    dim3 gp(NDIM / 128, MTOT / 128, 1);
    gemm_mma<<<gp, 256, GEMM_SMEM>>>(nullptr, Wo, nullptr, nullptr, out);
}

// round 10
// speedup vs baseline: 3.8607x; 1.0803x over previous
#include <cuda_runtime.h>
#include <cuda_bf16.h>
#include <math.h>
#include <stdint.h>

// Shapes fixed: B=4, S=2048, D=1024, H=16, dh=64.
#define BATCH     4
#define SEQ       2048
#define DMODEL    1024
#define NHEADS    16
#define HDIM      64
#define MTOT      (BATCH * SEQ)      // 8192
#define KDIM      DMODEL
#define NDIM      DMODEL
#define QKV_ELEMS (BATCH * NHEADS * SEQ * HDIM)   // 8388608

// Scratch: 6 x 16 MiB bf16 + 32 MiB fp32 + tables = 128.5 MiB total
// (footprint proven safe against the allocation guard in rounds 1/4/5/8/9).
__device__ __nv_bfloat16 g_qh[QKV_ELEMS];   // Q hi/lo: scaled 1/8, RoPE'd, [b,h,s,d]
__device__ __nv_bfloat16 g_ql[QKV_ELEMS];
__device__ __nv_bfloat16 g_kh[QKV_ELEMS];   // K hi/lo: RoPE'd, [b,h,s,d]
__device__ __nv_bfloat16 g_kl[QKV_ELEMS];
__device__ __nv_bfloat16 g_vh[QKV_ELEMS];   // V hi/lo TRANSPOSED: [b,h,d,s]
__device__ __nv_bfloat16 g_vl[QKV_ELEMS];
__device__ float         g_o [BATCH * SEQ * DMODEL];
__device__ float         g_cos[SEQ * (HDIM / 2)];
__device__ float         g_sin[SEQ * (HDIM / 2)];

// ---------------------------------------------------------------------------
// helpers
// ---------------------------------------------------------------------------
__device__ __forceinline__ uint32_t f2tf32(float x) {
    uint32_t u;
    asm("cvt.rna.tf32.f32 %0, %1;" : "=r"(u) : "f"(x));
    return u;
}
__device__ __forceinline__ void mma_tf32(float c[4], const uint32_t a[4],
                                         uint32_t b0, uint32_t b1) {
    asm volatile(
        "mma.sync.aligned.m16n8k8.row.col.f32.tf32.tf32.f32 "
        "{%0,%1,%2,%3}, {%4,%5,%6,%7}, {%8,%9}, {%0,%1,%2,%3};"
        : "+f"(c[0]), "+f"(c[1]), "+f"(c[2]), "+f"(c[3])
        : "r"(a[0]), "r"(a[1]), "r"(a[2]), "r"(a[3]), "r"(b0), "r"(b1));
}
__device__ __forceinline__ void mma_bf16(float c[4], const uint32_t a[4],
                                         uint32_t b0, uint32_t b1) {
    asm volatile(
        "mma.sync.aligned.m16n8k16.row.col.f32.bf16.bf16.f32 "
        "{%0,%1,%2,%3}, {%4,%5,%6,%7}, {%8,%9}, {%0,%1,%2,%3};"
        : "+f"(c[0]), "+f"(c[1]), "+f"(c[2]), "+f"(c[3])
        : "r"(a[0]), "r"(a[1]), "r"(a[2]), "r"(a[3]), "r"(b0), "r"(b1));
}
// ldmatrix x4: four 8x8 b16 tiles; lane l supplies row (l&7) of tile (l>>3).
__device__ __forceinline__ void ldsm_x4(uint32_t r[4], uint32_t addr) {
    asm volatile("ldmatrix.sync.aligned.m8n8.x4.shared.b16 {%0,%1,%2,%3}, [%4];"
        : "=r"(r[0]), "=r"(r[1]), "=r"(r[2]), "=r"(r[3]) : "r"(addr));
}
// pack two fp32 -> bf16x2; first operand lands in the HIGH half.
__device__ __forceinline__ uint32_t packbf(float hi, float lo) {
    uint32_t r;
    asm("cvt.rn.bf16x2.f32 %0, %1, %2;" : "=r"(r) : "f"(hi), "f"(lo));
    return r;
}
__device__ __forceinline__ uint4 cvt4(float4 f) {
    return make_uint4(f2tf32(f.x), f2tf32(f.y), f2tf32(f.z), f2tf32(f.w));
}
__device__ __forceinline__ uint32_t smem_u32(const void* p) {
    uint32_t a;
    asm("{ .reg .u64 t; cvta.to.shared.u64 t, %1; cvt.u32.u64 %0, t; }"
        : "=r"(a) : "l"(p));
    return a;
}

// ---------------------------------------------------------------------------
// RoPE table
// ---------------------------------------------------------------------------
__global__ void rope_table_kernel(const int* __restrict__ tpos) {
    int s = blockIdx.x;
    int f = threadIdx.x;
    double inv = exp(-(2.0 * (double)f / (double)HDIM) * log(10000.0));
    double a = (double)tpos[s] * inv;
    g_cos[s * 32 + f] = (float)cos(a);
    g_sin[s * 32 + f] = (float)sin(a);
}

// ---------------------------------------------------------------------------
// tf32 mma.sync GEMM, register-double-buffered fill + ldmatrix frag loads.
// C[m][n] = sum_k A[m][k] * W[n][k]. CTA 128x128, 8 warps (4m x 2n),
// warp tile 32x64. KC=32 chunks, single smem stage (pitch 36).
// Epilogues:
//  mode 0: Q -> RoPE, *0.125, bf16 hi/lo split -> g_qh/g_ql [b,h,s,d]
//  mode 1: K -> RoPE,          bf16 hi/lo split -> g_kh/g_kl [b,h,s,d]
//  mode 2: V ->                bf16 hi/lo split -> g_vh/g_vl TRANSPOSED [b,h,d,s]
//  mode 3: plain fp32 store to Cout (A = g_o).
// ---------------------------------------------------------------------------
#define KC      32
#define PITCH   36
#define NCHUNK  (KDIM / KC)               // 32
#define GEMM_SMEM (2 * 128 * PITCH * 4)   // A + B single stage = 36864 bytes

__global__ __launch_bounds__(256, 2)
void gemm_mma(const float* __restrict__ A,
              const float* __restrict__ W0, const float* __restrict__ W1,
              const float* __restrict__ W2,
              float* __restrict__ Cout) {
    extern __shared__ __align__(16) uint32_t smu[];
    uint32_t* As = smu;                  // [128][PITCH]
    uint32_t* Bs = smu + 128 * PITCH;

    const int mode = Cout ? 3 : blockIdx.z;
    const float* W = (mode == 1) ? W1 : (mode == 2) ? W2 : W0;
    const float* Ap = A ? A : g_o;

    const int tid = threadIdx.x;
    const int warp = tid >> 5, lane = tid & 31;
    const int wm = warp >> 1, wn = warp & 1;
    const int g = lane >> 2, t = lane & 3;
    const int m0 = blockIdx.y * 128, n0 = blockIdx.x * 128;

    // ldmatrix per-lane addresses (byte offsets in shared space)
    const uint32_t sbA = smem_u32(As), sbB = smem_u32(Bs);
    const int lrow = lane & 7, lm = lane >> 3;
    uint32_t aAddr[2], bAddr[4];
#pragma unroll
    for (int mf = 0; mf < 2; mf++) {
        int row = wm * 32 + mf * 16 + (lm & 1) * 8 + lrow;  // a0,a1,a2,a3
        int col = (lm >> 1) * 4;
        aAddr[mf] = sbA + (uint32_t)(row * PITCH + col) * 4;
    }
#pragma unroll
    for (int fg = 0; fg < 4; fg++) {
        int row = wn * 64 + (2 * fg + (lm >> 1)) * 8 + lrow; // b0/b1 of f, f+1
        int col = (lm & 1) * 4;
        bAddr[fg] = sbB + (uint32_t)(row * PITCH + col) * 4;
    }

    // fill mapping: thread covers rows r0+32j (j<4) at k-cols q0..q0+3
    const int r0 = tid >> 3, q0 = (tid & 7) * 4;
    const float* Aptr = Ap + (size_t)(m0 + r0) * KDIM + q0;
    const float* Wptr = W  + (size_t)(n0 + r0) * KDIM + q0;

    float c[2][8][4];
#pragma unroll
    for (int mf = 0; mf < 2; mf++)
#pragma unroll
        for (int f = 0; f < 8; f++)
#pragma unroll
            for (int i = 0; i < 4; i++) c[mf][f][i] = 0.f;

    float4 ra[4], rb[4];
    // prologue: chunk 0 -> regs -> smem
#pragma unroll
    for (int j = 0; j < 4; j++) {
        ra[j] = *(const float4*)(Aptr + (size_t)(32 * j) * KDIM);
        rb[j] = *(const float4*)(Wptr + (size_t)(32 * j) * KDIM);
    }
#pragma unroll
    for (int j = 0; j < 4; j++) {
        const int r = r0 + 32 * j;
        *(uint4*)(As + r * PITCH + q0) = cvt4(ra[j]);
        *(uint4*)(Bs + r * PITCH + q0) = cvt4(rb[j]);
    }
    __syncthreads();

    for (int ch = 0; ch < NCHUNK; ch++) {
        // issue next chunk's loads now; latency hides under the MMA phase
        if (ch + 1 < NCHUNK) {
            const float* An = Aptr + (ch + 1) * KC;
            const float* Wn = Wptr + (ch + 1) * KC;
#pragma unroll
            for (int j = 0; j < 4; j++) {
                ra[j] = *(const float4*)(An + (size_t)(32 * j) * KDIM);
                rb[j] = *(const float4*)(Wn + (size_t)(32 * j) * KDIM);
            }
        }

        // MMA phase on current smem contents (ldmatrix frag loads)
#pragma unroll
        for (int ks = 0; ks < 4; ks++) {
            const uint32_t kb = ks * 32;            // 8 u32 = 32 bytes per step
            uint32_t a[2][4];
            ldsm_x4(a[0], aAddr[0] + kb);
            ldsm_x4(a[1], aAddr[1] + kb);
#pragma unroll
            for (int fg = 0; fg < 4; fg++) {
                uint32_t bb[4];
                ldsm_x4(bb, bAddr[fg] + kb);
                mma_tf32(c[0][2 * fg],     a[0], bb[0], bb[1]);
                mma_tf32(c[1][2 * fg],     a[1], bb[0], bb[1]);
                mma_tf32(c[0][2 * fg + 1], a[0], bb[2], bb[3]);
                mma_tf32(c[1][2 * fg + 1], a[1], bb[2], bb[3]);
            }
        }
        __syncthreads();   // all warps done reading before overwrite

        if (ch + 1 < NCHUNK) {
#pragma unroll
            for (int j = 0; j < 4; j++) {
                const int r = r0 + 32 * j;
                *(uint4*)(As + r * PITCH + q0) = cvt4(ra[j]);
                *(uint4*)(Bs + r * PITCH + q0) = cvt4(rb[j]);
            }
            __syncthreads();   // stores visible before next MMA phase
        }
    }

    // Epilogue. c[mf][f]: rows (g, g+8), cols (2t, 2t+1) — RoPE pairs.
#pragma unroll
    for (int mf = 0; mf < 2; mf++) {
#pragma unroll
        for (int f = 0; f < 8; f++) {
            const float* cc = c[mf][f];
            const int col = n0 + wn * 64 + f * 8 + 2 * t;
            const int rbase = m0 + wm * 32 + mf * 16 + g;
#pragma unroll
            for (int half = 0; half < 2; half++) {
                const int m = rbase + half * 8;
                float v1 = cc[half * 2], v2 = cc[half * 2 + 1];
                if (mode == 3) {
                    *(float2*)(Cout + (size_t)m * NDIM + col) = make_float2(v1, v2);
                } else {
                    const int b = m >> 11, s = m & 2047;
                    const int h = col >> 6, d = col & 63;   // d even
                    if (mode < 2) {     // RoPE for Q and K
                        const float cs = g_cos[s * 32 + (d >> 1)];
                        const float sn = g_sin[s * 32 + (d >> 1)];
                        float r1 = v1 * cs - v2 * sn;
                        float r2 = v1 * sn + v2 * cs;
                        if (mode == 0) { r1 *= 0.125f; r2 *= 0.125f; }
                        v1 = r1; v2 = r2;
                    }
                    __nv_bfloat16 h1 = __float2bfloat16(v1);
                    __nv_bfloat16 h2 = __float2bfloat16(v2);
                    __nv_bfloat16 l1 = __float2bfloat16(v1 - __bfloat162float(h1));
                    __nv_bfloat16 l2 = __float2bfloat16(v2 - __bfloat162float(h2));
                    if (mode == 2) {    // V transposed: [b,h,d,s]
                        const size_t vb =
                            ((size_t)(b * NHEADS + h) * HDIM + d) * SEQ + s;
                        g_vh[vb] = h1;       g_vl[vb] = l1;
                        g_vh[vb + SEQ] = h2; g_vl[vb + SEQ] = l2;
                    } else {            // Q/K: [b,h,s,d], pair = one u32
                        const size_t base =
                            ((size_t)(b * NHEADS + h) * SEQ + s) * HDIM + d;
                        uint32_t hp = ((uint32_t)__bfloat16_as_ushort(h2) << 16)
                                    | __bfloat16_as_ushort(h1);
                        uint32_t lp = ((uint32_t)__bfloat16_as_ushort(l2) << 16)
                                    | __bfloat16_as_ushort(l1);
                        if (mode == 0) {
                            *(uint32_t*)(g_qh + base) = hp;
                            *(uint32_t*)(g_ql + base) = lp;
                        } else {
                            *(uint32_t*)(g_kh + base) = hp;
                            *(uint32_t*)(g_kl + base) = lp;
                        }
                    }
                }
            }
        }
    }
}

// ---------------------------------------------------------------------------
// Causal flash attention: bf16 m16n8k16 mma, 3-product hi/lo split, ldmatrix
// frag loads. Br=Bc=64, 128 threads (4 warps x 16 Q-rows). Q frags in regs;
// K/V tiles plain bf16 copies; P C-frags feed PV A-frags (no shfl).
// smem: Kh,Kl,Vh,Vl @ 64 x 72 bf16 (pitch 36 u32).
// ---------------------------------------------------------------------------
#define KP 36                        // u32 pitch
#define KTSZ (64 * KP)               // 2304 u32 per tile
#define ATTN_SMEM (4 * KTSZ * 4)     // 36864 bytes

__global__ __launch_bounds__(128)
void flash_bf16() {
    extern __shared__ __align__(16) uint32_t sm[];
    uint32_t* Khs = sm;
    uint32_t* Kls = sm + KTSZ;
    uint32_t* Vhs = sm + 2 * KTSZ;
    uint32_t* Vls = sm + 3 * KTSZ;

    const int qt = gridDim.x - 1 - (int)blockIdx.x;   // heavy tiles first
    const int bh = blockIdx.y;
    const int tid = threadIdx.x;
    const int warp = tid >> 5, lane = tid & 31;
    const int g = lane >> 2, t = lane & 3;
    const int wr = warp * 16;

    // ldmatrix per-lane address pattern (shared byte offsets, Khs-relative)
    const uint32_t smb = smem_u32(sm);
    const int lrow = lane & 7, lm = lane >> 3;
    uint32_t pat[4];
#pragma unroll
    for (int jg = 0; jg < 4; jg++) {
        int row = (2 * jg + (lm >> 1)) * 8 + lrow;   // (b0,b1) of j, j+1
        int col = (lm & 1) * 4;
        pat[jg] = smb + (uint32_t)(row * KP + col) * 4;
    }

    // ---- Q fragments -> registers (u32 = bf16x2, k-pairs 2t,2t+1) ----
    const uint32_t* Qhg = (const uint32_t*)g_qh;
    const uint32_t* Qlg = (const uint32_t*)g_ql;
    const size_t qrow0 = (((size_t)bh * SEQ + qt * 64 + wr + g) * HDIM) >> 1;
    const size_t qrow1 = qrow0 + (8 * HDIM >> 1);
    uint32_t qh[4][4], ql[4][4];
#pragma unroll
    for (int k0 = 0; k0 < 4; k0++) {
        const int o8 = 8 * k0 + t;
        qh[k0][0] = Qhg[qrow0 + o8];     ql[k0][0] = Qlg[qrow0 + o8];
        qh[k0][1] = Qhg[qrow1 + o8];     ql[k0][1] = Qlg[qrow1 + o8];
        qh[k0][2] = Qhg[qrow0 + o8 + 4]; ql[k0][2] = Qlg[qrow0 + o8 + 4];
        qh[k0][3] = Qhg[qrow1 + o8 + 4]; ql[k0][3] = Qlg[qrow1 + o8 + 4];
    }

    float m_i[2] = {-1e30f, -1e30f};
    float l_i[2] = {0.f, 0.f};
    float o[8][4];
#pragma unroll
    for (int j = 0; j < 8; j++)
#pragma unroll
        for (int i = 0; i < 4; i++) o[j][i] = 0.f;

    const uint32_t* Khg = (const uint32_t*)g_kh;
    const uint32_t* Klg = (const uint32_t*)g_kl;
    const uint32_t* Vhg = (const uint32_t*)g_vh;
    const uint32_t* Vlg = (const uint32_t*)g_vl;

    for (int kt = 0; kt <= qt; kt++) {
        __syncthreads();   // previous iteration's MMAs done before overwrite
        const size_t kbase = (((size_t)bh * SEQ + kt * 64) * HDIM) >> 1;
        const size_t vbase = (((size_t)bh * HDIM) * SEQ + kt * 64) >> 1;
#pragma unroll
        for (int j = 0; j < 4; j++) {
            int it = tid + j * 128;
            int r = it >> 3;
            int cu = (it & 7) * 4;                 // u32 offset within row
            const size_t ks = kbase + r * 32 + cu; // K row stride 32 u32
            const size_t vs = vbase + (size_t)r * (SEQ / 2) + cu;
            *(uint4*)(Khs + r * KP + cu) = *(const uint4*)(Khg + ks);
            *(uint4*)(Kls + r * KP + cu) = *(const uint4*)(Klg + ks);
            *(uint4*)(Vhs + r * KP + cu) = *(const uint4*)(Vhg + vs);
            *(uint4*)(Vls + r * KP + cu) = *(const uint4*)(Vlg + vs);
        }
        __syncthreads();

        // ---- S = Q K^T (hh + hl + lh), 4 k-steps of 16 ----
        float c[8][4];
#pragma unroll
        for (int j = 0; j < 8; j++)
#pragma unroll
            for (int i = 0; i < 4; i++) c[j][i] = 0.f;

#pragma unroll
        for (int k0 = 0; k0 < 4; k0++) {
            const uint32_t kb = k0 * 32;           // 8 u32 per step
#pragma unroll
            for (int jg = 0; jg < 4; jg++) {
                uint32_t kh4[4], kl4[4];
                ldsm_x4(kh4, pat[jg] + kb);                     // Khs
                ldsm_x4(kl4, pat[jg] + KTSZ * 4 + kb);          // Kls
                const int j0 = 2 * jg, j1 = 2 * jg + 1;
                mma_bf16(c[j0], qh[k0], kh4[0], kh4[1]);
                mma_bf16(c[j0], qh[k0], kl4[0], kl4[1]);
                mma_bf16(c[j0], ql[k0], kh4[0], kh4[1]);
                mma_bf16(c[j1], qh[k0], kh4[2], kh4[3]);
                mma_bf16(c[j1], qh[k0], kl4[2], kl4[3]);
                mma_bf16(c[j1], ql[k0], kh4[2], kh4[3]);
            }
        }

        // ---- causal mask (diagonal tile only) ----
        if (kt == qt) {
#pragma unroll
            for (int j = 0; j < 8; j++) {
                const int col0 = j * 8 + 2 * t;
                const int r0 = wr + g, r1 = wr + g + 8;
                if (col0 > r0)     c[j][0] = -1e30f;
                if (col0 + 1 > r0) c[j][1] = -1e30f;
                if (col0 > r1)     c[j][2] = -1e30f;
                if (col0 + 1 > r1) c[j][3] = -1e30f;
            }
        }

        // ---- online softmax (rows g and g+8) ----
        float mx0 = -1e30f, mx1 = -1e30f;
#pragma unroll
        for (int j = 0; j < 8; j++) {
            mx0 = fmaxf(mx0, fmaxf(c[j][0], c[j][1]));
            mx1 = fmaxf(mx1, fmaxf(c[j][2], c[j][3]));
        }
#pragma unroll
        for (int off = 1; off < 4; off <<= 1) {
            mx0 = fmaxf(mx0, __shfl_xor_sync(0xffffffffu, mx0, off));
            mx1 = fmaxf(mx1, __shfl_xor_sync(0xffffffffu, mx1, off));
        }
        const float mn0 = fmaxf(m_i[0], mx0);
        const float mn1 = fmaxf(m_i[1], mx1);
        const float al0 = __expf(m_i[0] - mn0);
        const float al1 = __expf(m_i[1] - mn1);
        float sum0 = 0.f, sum1 = 0.f;
#pragma unroll
        for (int j = 0; j < 8; j++) {
            c[j][0] = __expf(c[j][0] - mn0);
            c[j][1] = __expf(c[j][1] - mn0);
            c[j][2] = __expf(c[j][2] - mn1);
            c[j][3] = __expf(c[j][3] - mn1);
            sum0 += c[j][0] + c[j][1];
            sum1 += c[j][2] + c[j][3];
        }
#pragma unroll
        for (int off = 1; off < 4; off <<= 1) {
            sum0 += __shfl_xor_sync(0xffffffffu, sum0, off);
            sum1 += __shfl_xor_sync(0xffffffffu, sum1, off);
        }
        l_i[0] = l_i[0] * al0 + sum0;
        l_i[1] = l_i[1] * al1 + sum1;
        m_i[0] = mn0; m_i[1] = mn1;
#pragma unroll
        for (int j = 0; j < 8; j++) {
            o[j][0] *= al0; o[j][1] *= al0;
            o[j][2] *= al1; o[j][3] *= al1;
        }

        // ---- O += P V. bf16 k16 A-frag == this thread's C-frag cols. ----
#pragma unroll
        for (int k0 = 0; k0 < 4; k0++) {
            const int j0 = 2 * k0, j1 = 2 * k0 + 1;
            uint32_t ph[4], pl[4];
            ph[0] = packbf(c[j0][1], c[j0][0]);
            ph[1] = packbf(c[j0][3], c[j0][2]);
            ph[2] = packbf(c[j1][1], c[j1][0]);
            ph[3] = packbf(c[j1][3], c[j1][2]);
#pragma unroll
            for (int i = 0; i < 4; i++) {
                const int jj = (i < 2) ? j0 : j1;
                const int bb = (i & 1) * 2;
                float h0 = __uint_as_float(ph[i] << 16);
                float h1 = __uint_as_float(ph[i] & 0xFFFF0000u);
                pl[i] = packbf(c[jj][bb + 1] - h1, c[jj][bb] - h0);
            }
            const uint32_t kb = k0 * 32;
#pragma unroll
            for (int jg = 0; jg < 4; jg++) {
                uint32_t vh4[4], vl4[4];
                ldsm_x4(vh4, pat[jg] + 2 * KTSZ * 4 + kb);      // Vhs
                ldsm_x4(vl4, pat[jg] + 3 * KTSZ * 4 + kb);      // Vls
                const int jo0 = 2 * jg, jo1 = 2 * jg + 1;
                mma_bf16(o[jo0], ph, vh4[0], vh4[1]);
                mma_bf16(o[jo0], ph, vl4[0], vl4[1]);
                mma_bf16(o[jo0], pl, vh4[0], vh4[1]);
                mma_bf16(o[jo1], ph, vh4[2], vh4[3]);
                mma_bf16(o[jo1], ph, vl4[2], vl4[3]);
                mma_bf16(o[jo1], pl, vh4[2], vh4[3]);
            }
        }
    }

    // ---- epilogue: O / l -> g_o [b, s, h*64 + d] ----
    const int b = bh >> 4, h = bh & 15;
    const float inv0 = 1.f / l_i[0];
    const float inv1 = 1.f / l_i[1];
    const int s0 = qt * 64 + wr + g;
    const int s1 = s0 + 8;
    float* row0 = g_o + ((size_t)b * SEQ + s0) * DMODEL + h * HDIM;
    float* row1 = g_o + ((size_t)b * SEQ + s1) * DMODEL + h * HDIM;
#pragma unroll
    for (int j = 0; j < 8; j++) {
        const int d = j * 8 + 2 * t;
        *(float2*)(row0 + d) = make_float2(o[j][0] * inv0, o[j][1] * inv0);
        *(float2*)(row1 + d) = make_float2(o[j][2] * inv1, o[j][3] * inv1);
    }
}

// ---------------------------------------------------------------------------
extern "C" void kernel_launch(void* const* d_in, const int* in_sizes, int n_in,
                              void* d_out, int out_size) {
    const float* x  = (const float*)d_in[0];
    const float* Wq = (const float*)d_in[1];
    const float* Wk = (const float*)d_in[2];
    const float* Wv = (const float*)d_in[3];
    const float* Wo = (const float*)d_in[4];
    const int* tpos = (const int*)d_in[5];
    float* out = (float*)d_out;

    rope_table_kernel<<<SEQ, 32>>>(tpos);

    dim3 gqkv(NDIM / 128, MTOT / 128, 3);
    gemm_mma<<<gqkv, 256, GEMM_SMEM>>>(x, Wq, Wk, Wv, nullptr);

    flash_bf16<<<dim3(SEQ / 64, BATCH * NHEADS), 128, ATTN_SMEM>>>();

    dim3 gp(NDIM / 128, MTOT / 128, 1);
    gemm_mma<<<gp, 256, GEMM_SMEM>>>(nullptr, Wo, nullptr, nullptr, out);
}